// round 15
// baseline (speedup 1.0000x reference)
#include <cuda_runtime.h>
#include <cuda_fp16.h>
#include <math.h>
#include <stdint.h>

#define NN 50000
#define EE 800000
#define HH 4
#define DD 64
#define HDIM 256
#define NETT 8
#define CCC 16

typedef unsigned long long ull;

// ---------------- scratch (static device globals; no allocs) ----------------
__device__ float g_feat[(size_t)NN * 32];      // layer-2 only: feat2|res2
__device__ __half g_feat16[(size_t)NN * HDIM];
__device__ float g_out[(size_t)NN * HDIM];
__device__ float g_el[NN * HH];
__device__ float g_er[NN * HH];
__device__ float g_logits[(size_t)EE * HH];
__device__ float g_a[(size_t)EE * HH];
__device__ float g_ra[(size_t)EE * HH];
__device__ float g_es3[3 * 32];
__device__ float g_B2[32 * HDIM];
__device__ float g_Wf[256 * (128 + 64 + 32)];
__device__ float g_cf[3 * 256];
__device__ int g_deg[NN];
__device__ int g_rowptr[NN + 1];
__device__ int g_fill[NN];
__device__ int g_src_csr[EE];
__device__ int g_et_csr[EE];

__device__ __forceinline__ float lrelu(float x) { return x > 0.f ? x : 0.2f * x; }

// packed f32x2 helpers
__device__ __forceinline__ ull pack2(float lo, float hi) {
    ull r;
    asm("mov.b64 %0, {%1, %2};" : "=l"(r) : "f"(lo), "f"(hi));
    return r;
}
__device__ __forceinline__ void unpack2(ull v, float& lo, float& hi) {
    asm("mov.b64 {%0, %1}, %2;" : "=f"(lo), "=f"(hi) : "l"(v));
}
__device__ __forceinline__ void ffma2(ull& d, ull a, ull b) {
    asm("fma.rn.f32x2 %0, %1, %2, %0;" : "+l"(d) : "l"(a), "l"(b));
}
__device__ __forceinline__ void hacc(float4& ac, float aw, ull v) {
    __half2 lo = *reinterpret_cast<__half2*>(&v);
    __half2 hi = *(reinterpret_cast<__half2*>(&v) + 1);
    float2 f01 = __half22float2(lo);
    float2 f23 = __half22float2(hi);
    ac.x += aw * f01.x;
    ac.y += aw * f01.y;
    ac.z += aw * f23.x;
    ac.w += aw * f23.y;
}

// ---------------- one-shot weight fusion ----------------
__global__ void k_wfuse_all(const float* __restrict__ Wg,
                            const float* __restrict__ W0, const float* __restrict__ W1,
                            const float* __restrict__ W2, const float* __restrict__ b0,
                            const float* __restrict__ b1, const float* __restrict__ b2,
                            float* __restrict__ Wf, float* __restrict__ cf) {
    int i = blockIdx.y;
    int j = threadIdx.x;
    const float* wg = Wg + i * 64;
    float s = 0.f;
    if (j < 128) {
#pragma unroll
        for (int k = 0; k < 64; k++) s += wg[k] * W0[k * 128 + j];
        Wf[i * 128 + j] = s;
    } else if (j < 192) {
        int jj = j - 128;
#pragma unroll
        for (int k = 0; k < 64; k++) s += wg[k] * W1[k * 64 + jj];
        Wf[256 * 128 + i * 64 + jj] = s;
    } else if (j < 224) {
        int jj = j - 192;
#pragma unroll
        for (int k = 0; k < 64; k++) s += wg[k] * W2[k * 32 + jj];
        Wf[256 * 192 + i * 32 + jj] = s;
    } else if (j < 227) {
        const float* b = (j == 224) ? b0 : (j == 225) ? b1 : b2;
#pragma unroll
        for (int k = 0; k < 64; k++) s += wg[k] * b[k];
        cf[(j - 224) * 256 + i] = s;
    }
}

// ---------------- CSR build ----------------
__global__ void k_zero_int(int* p, int n) {
    int i = blockIdx.x * blockDim.x + threadIdx.x;
    if (i < n) p[i] = 0;
}

__global__ void k_hist(const int* __restrict__ dst) {
    int e = blockIdx.x * blockDim.x + threadIdx.x;
    if (e < EE) atomicAdd(&g_deg[dst[e]], 1);
}

__global__ void k_scan() {
    __shared__ int sums[1024];
    const int T = 1024;
    const int CH = (NN + T - 1) / T;
    int t = threadIdx.x;
    int start = t * CH;
    int lim = min(start + CH, NN);
    int s = 0;
    for (int i = start; i < lim; i++) s += g_deg[i];
    sums[t] = s;
    __syncthreads();
    for (int off = 1; off < T; off <<= 1) {
        int v = (t >= off) ? sums[t - off] : 0;
        __syncthreads();
        sums[t] += v;
        __syncthreads();
    }
    int run = (t == 0) ? 0 : sums[t - 1];
    for (int i = start; i < lim; i++) {
        g_rowptr[i] = run;
        g_fill[i] = run;
        run += g_deg[i];
    }
    if (t == T - 1) g_rowptr[NN] = run;
}

__global__ void k_scatter(const int* __restrict__ src, const int* __restrict__ dst,
                          const int* __restrict__ et) {
    int e = blockIdx.x * blockDim.x + threadIdx.x;
    if (e < EE) {
        int p = atomicAdd(&g_fill[dst[e]], 1);
        g_src_csr[p] = src[e];
        g_et_csr[p] = et[e];
    }
}

// ---------------- skinny GEMM (128x32x32) + fused el2/er2 epilogue ----------------
__global__ void gemm_nt_s(const float* __restrict__ A, const float* __restrict__ B,
                          float* __restrict__ C, const float* __restrict__ al2,
                          const float* __restrict__ ar2, float* __restrict__ el,
                          float* __restrict__ er, int M, int K) {
    const int SBM = 128, SBN = 32, SBK = 32;
    __shared__ float As[SBK][SBM];
    __shared__ float Bs[SBK][SBN];
    int t = threadIdx.x;
    int tx = t & 7, ty = t >> 3;
    int bm = blockIdx.x * SBM;
    float acc[4][4] = {};
    for (int k0 = 0; k0 < K; k0 += SBK) {
#pragma unroll
        for (int q = 0; q < 4; q++) {
            int f = t + q * 256;
            int row = f >> 3, c4 = f & 7;
            int gr = bm + row;
            float4 v = make_float4(0.f, 0.f, 0.f, 0.f);
            if (gr < M) v = *reinterpret_cast<const float4*>(A + (size_t)gr * K + k0 + c4 * 4);
            As[c4 * 4 + 0][row] = v.x;
            As[c4 * 4 + 1][row] = v.y;
            As[c4 * 4 + 2][row] = v.z;
            As[c4 * 4 + 3][row] = v.w;
        }
        if (t < 256) {
            int row = t >> 3, c4 = t & 7;
            float4 w = *reinterpret_cast<const float4*>(B + (size_t)row * K + k0 + c4 * 4);
            Bs[c4 * 4 + 0][row] = w.x;
            Bs[c4 * 4 + 1][row] = w.y;
            Bs[c4 * 4 + 2][row] = w.z;
            Bs[c4 * 4 + 3][row] = w.w;
        }
        __syncthreads();
#pragma unroll
        for (int kk = 0; kk < SBK; kk++) {
            float4 ra = *reinterpret_cast<const float4*>(&As[kk][ty * 4]);
            float4 rb = *reinterpret_cast<const float4*>(&Bs[kk][tx * 4]);
            float av[4] = {ra.x, ra.y, ra.z, ra.w};
            float bv[4] = {rb.x, rb.y, rb.z, rb.w};
#pragma unroll
            for (int i = 0; i < 4; i++)
#pragma unroll
                for (int j = 0; j < 4; j++) acc[i][j] += av[i] * bv[j];
        }
        __syncthreads();
    }
    float alv[4] = {0.f, 0.f, 0.f, 0.f}, arv[4] = {0.f, 0.f, 0.f, 0.f};
    if (tx < 4) {
#pragma unroll
        for (int j = 0; j < 4; j++) {
            alv[j] = __ldg(&al2[tx * 4 + j]);
            arv[j] = __ldg(&ar2[tx * 4 + j]);
        }
    }
#pragma unroll
    for (int i = 0; i < 4; i++) {
        int gr = bm + ty * 4 + i;
        bool valid = gr < M;
        if (valid) {
            float4 v;
            v.x = acc[i][0];
            v.y = acc[i][1];
            v.z = acc[i][2];
            v.w = acc[i][3];
            *reinterpret_cast<float4*>(C + (size_t)gr * SBN + tx * 4) = v;
        }
        float pel = 0.f, per = 0.f;
        if (tx < 4) {
#pragma unroll
            for (int j = 0; j < 4; j++) {
                pel += acc[i][j] * alv[j];
                per += acc[i][j] * arv[j];
            }
        }
#pragma unroll
        for (int o = 1; o < 8; o <<= 1) {
            pel += __shfl_xor_sync(0xffffffffu, pel, o);
            per += __shfl_xor_sync(0xffffffffu, per, o);
        }
        if (tx == 0 && valid) {
            el[gr] = pel;
            er[gr] = per;
        }
    }
}

// ---------------- feat GEMM body (128x128x16, FFMA2, fused bias + el/er + fp16 out) ----------------
#define GBM 128
#define GBK 16

__device__ __forceinline__ void feat_body(int bx, int by, const float* __restrict__ A,
                                          const float* __restrict__ B,
                                          const float* __restrict__ cbias,
                                          __half* __restrict__ F16,
                                          const float* __restrict__ al,
                                          const float* __restrict__ ar,
                                          float* __restrict__ el, float* __restrict__ er,
                                          int M, int K) {
    __shared__ float2 As[2][GBK][GBM];
    __shared__ float Bs[2][GBK][128];
    int t = threadIdx.x;
    int tx = t & 15, ty = t >> 4;
    int bm = bx * GBM, bn = by * 128;
    int lrow = t >> 2;
    int lc4 = t & 3;

    float4 pa[2], pb[2];
    auto ldg = [&](int k0) {
#pragma unroll
        for (int q = 0; q < 2; q++) {
            int row = lrow + q * 64;
            int gr = bm + row;
            pa[q] = make_float4(0.f, 0.f, 0.f, 0.f);
            if (gr < M) pa[q] = *reinterpret_cast<const float4*>(A + (size_t)gr * K + k0 + lc4 * 4);
            int gc = bn + row;
            pb[q] = *reinterpret_cast<const float4*>(B + (size_t)gc * K + k0 + lc4 * 4);
        }
    };
    auto sts = [&](int buf) {
#pragma unroll
        for (int q = 0; q < 2; q++) {
            int row = lrow + q * 64;
            As[buf][lc4 * 4 + 0][row] = make_float2(pa[q].x, pa[q].x);
            As[buf][lc4 * 4 + 1][row] = make_float2(pa[q].y, pa[q].y);
            As[buf][lc4 * 4 + 2][row] = make_float2(pa[q].z, pa[q].z);
            As[buf][lc4 * 4 + 3][row] = make_float2(pa[q].w, pa[q].w);
            Bs[buf][lc4 * 4 + 0][row] = pb[q].x;
            Bs[buf][lc4 * 4 + 1][row] = pb[q].y;
            Bs[buf][lc4 * 4 + 2][row] = pb[q].z;
            Bs[buf][lc4 * 4 + 3][row] = pb[q].w;
        }
    };

    ull acc2[8][4];
#pragma unroll
    for (int i = 0; i < 8; i++)
#pragma unroll
        for (int j = 0; j < 4; j++) acc2[i][j] = 0ull;

    int nt = K / GBK;
    ldg(0);
    sts(0);
    __syncthreads();
    for (int it = 0; it < nt; it++) {
        int cur = it & 1;
        bool has = (it + 1) < nt;
        if (has) ldg((it + 1) * GBK);
#pragma unroll
        for (int kk = 0; kk < GBK; kk++) {
            const ull* ap0 = reinterpret_cast<const ull*>(&As[cur][kk][ty * 4]);
            const ull* ap1 = reinterpret_cast<const ull*>(&As[cur][kk][ty * 4 + 64]);
            ull aa[8];
            aa[0] = ap0[0]; aa[1] = ap0[1]; aa[2] = ap0[2]; aa[3] = ap0[3];
            aa[4] = ap1[0]; aa[5] = ap1[1]; aa[6] = ap1[2]; aa[7] = ap1[3];
            // B pairs read directly as 64-bit lanes (adjacent floats) — no packing
            const ull* bp0 = reinterpret_cast<const ull*>(&Bs[cur][kk][tx * 4]);
            const ull* bp1 = reinterpret_cast<const ull*>(&Bs[cur][kk][tx * 4 + 64]);
            ull b2[4];
            b2[0] = bp0[0];
            b2[1] = bp0[1];
            b2[2] = bp1[0];
            b2[3] = bp1[1];
#pragma unroll
            for (int i = 0; i < 8; i++)
#pragma unroll
                for (int j = 0; j < 4; j++) ffma2(acc2[i][j], aa[i], b2[j]);
        }
        if (has) sts(cur ^ 1);
        __syncthreads();
    }

    int h0 = bn >> 6;
    float alv[2][4], arv[2][4], cv[2][4];
#pragma unroll
    for (int hj = 0; hj < 2; hj++)
#pragma unroll
        for (int j = 0; j < 4; j++) {
            alv[hj][j] = __ldg(&al[(h0 + hj) * 64 + tx * 4 + j]);
            arv[hj][j] = __ldg(&ar[(h0 + hj) * 64 + tx * 4 + j]);
            cv[hj][j] = cbias ? __ldg(&cbias[bn + hj * 64 + tx * 4 + j]) : 0.f;
        }
#pragma unroll
    for (int hi = 0; hi < 2; hi++) {
#pragma unroll
        for (int i = 0; i < 4; i++) {
            int gr = bm + ty * 4 + hi * 64 + i;
            bool valid = gr < M;
            float pel[2], per[2];
#pragma unroll
            for (int hj = 0; hj < 2; hj++) {
                float4 v;
                unpack2(acc2[hi * 4 + i][hj * 2 + 0], v.x, v.y);
                unpack2(acc2[hi * 4 + i][hj * 2 + 1], v.z, v.w);
                v.x += cv[hj][0];
                v.y += cv[hj][1];
                v.z += cv[hj][2];
                v.w += cv[hj][3];
                if (valid) {
                    __half2 lo = __floats2half2_rn(v.x, v.y);
                    __half2 hi2 = __floats2half2_rn(v.z, v.w);
                    ull pk;
                    asm("mov.b64 %0, {%1, %2};" : "=l"(pk)
                        : "r"(*reinterpret_cast<uint32_t*>(&lo)), "r"(*reinterpret_cast<uint32_t*>(&hi2)));
                    *reinterpret_cast<ull*>(F16 + (size_t)gr * HDIM + bn + hj * 64 + tx * 4) = pk;
                }
                pel[hj] = v.x * alv[hj][0] + v.y * alv[hj][1] + v.z * alv[hj][2] + v.w * alv[hj][3];
                per[hj] = v.x * arv[hj][0] + v.y * arv[hj][1] + v.z * arv[hj][2] + v.w * arv[hj][3];
            }
#pragma unroll
            for (int o = 1; o < 16; o <<= 1) {
                pel[0] += __shfl_xor_sync(0xffffffffu, pel[0], o);
                pel[1] += __shfl_xor_sync(0xffffffffu, pel[1], o);
                per[0] += __shfl_xor_sync(0xffffffffu, per[0], o);
                per[1] += __shfl_xor_sync(0xffffffffu, per[1], o);
            }
            if (tx == 0 && valid) {
                el[gr * 4 + h0] = pel[0];
                el[gr * 4 + h0 + 1] = pel[1];
                er[gr * 4 + h0] = per[0];
                er[gr * 4 + h0 + 1] = per[1];
            }
        }
    }
}

// layer-1 feat GEMM (single segment)
__global__ __launch_bounds__(256, 2) void gemm_feat(const float* __restrict__ A,
                                                    const float* __restrict__ B,
                                                    __half* __restrict__ F16,
                                                    const float* __restrict__ al,
                                                    const float* __restrict__ ar,
                                                    float* __restrict__ el,
                                                    float* __restrict__ er, int M, int K) {
    feat_body(blockIdx.x, blockIdx.y, A, B, nullptr, F16, al, ar, el, er, M, K);
}

// fused input-proj + layer-0 feat GEMM: 3 segments in one launch
#define SEG0 157
#define SEG1 118

__global__ __launch_bounds__(256, 2) void gemm_feat_in(const float* __restrict__ x0,
                                                       const float* __restrict__ x1,
                                                       const float* __restrict__ x2,
                                                       const float* __restrict__ Wf,
                                                       const float* __restrict__ cf,
                                                       __half* __restrict__ F16,
                                                       const float* __restrict__ al,
                                                       const float* __restrict__ ar,
                                                       float* __restrict__ el,
                                                       float* __restrict__ er) {
    int bx = blockIdx.x, by = blockIdx.y;
    if (bx < SEG0) {
        feat_body(bx, by, x0, Wf, cf, F16, al, ar, el, er, 20000, 128);
    } else if (bx < SEG0 + SEG1) {
        feat_body(bx - SEG0, by, x1, Wf + 256 * 128, cf + 256, F16 + (size_t)20000 * HDIM, al, ar,
                  el + 20000 * 4, er + 20000 * 4, 15000, 64);
    } else {
        feat_body(bx - SEG0 - SEG1, by, x2, Wf + 256 * 192, cf + 512, F16 + (size_t)35000 * HDIM,
                  al, ar, el + 35000 * 4, er + 35000 * 4, 15000, 32);
    }
}

// ---------------- edge-type attention term ----------------
__global__ void k_es(const float* __restrict__ etab, const float* __restrict__ We,
                     const float* __restrict__ ae, float* __restrict__ es, int H) {
    int b = blockIdx.x;
    int t = b / H, h = b % H;
    int d = threadIdx.x;
    const float* wr = We + (size_t)(h * 64 + d) * 64;
    const float* er = etab + t * 64;
    float dot = 0.f;
#pragma unroll
    for (int k = 0; k < 64; k++) dot += er[k] * wr[k];
    float v = ae[h * 64 + d] * dot;
    __shared__ float sm[64];
    sm[d] = v;
    __syncthreads();
    if (d < 32) {
        float x = sm[d] + sm[d + 32];
#pragma unroll
        for (int o = 16; o; o >>= 1) x += __shfl_xor_sync(0xffffffffu, x, o);
        if (d == 0) es[t * H + h] = x;
    }
}

// ---------------- fused logits + softmax (H=4), register-resident for deg<=128 ----------------
__global__ void k_attn4(const float* __restrict__ el, const float* __restrict__ er,
                        const float* __restrict__ es, float* __restrict__ aout,
                        const float* __restrict__ ramix) {
    int w = (blockIdx.x * blockDim.x + threadIdx.x) >> 5;
    int lane = threadIdx.x & 31;
    if (w >= NN) return;
    int st = g_rowptr[w], en = g_rowptr[w + 1];
    int deg = en - st;
    float4 ern = *reinterpret_cast<const float4*>(&er[w * 4]);
    float4 mx = make_float4(-1e30f, -1e30f, -1e30f, -1e30f);

    if (deg <= 128) {
        float4 lg[4];
        int nc = 0;
#pragma unroll
        for (int c = 0; c < 4; c++) {
            int k = st + lane + c * 32;
            if (k < en) {
                int s = g_src_csr[k], t = g_et_csr[k];
                float4 a = *reinterpret_cast<const float4*>(&el[s * 4]);
                float4 cc = *reinterpret_cast<const float4*>(&es[t * 4]);
                lg[c].x = lrelu(a.x + ern.x + cc.x);
                lg[c].y = lrelu(a.y + ern.y + cc.y);
                lg[c].z = lrelu(a.z + ern.z + cc.z);
                lg[c].w = lrelu(a.w + ern.w + cc.w);
                mx.x = fmaxf(mx.x, lg[c].x);
                mx.y = fmaxf(mx.y, lg[c].y);
                mx.z = fmaxf(mx.z, lg[c].z);
                mx.w = fmaxf(mx.w, lg[c].w);
                nc = c + 1;
            }
        }
#pragma unroll
        for (int o = 16; o; o >>= 1) {
            mx.x = fmaxf(mx.x, __shfl_xor_sync(0xffffffffu, mx.x, o));
            mx.y = fmaxf(mx.y, __shfl_xor_sync(0xffffffffu, mx.y, o));
            mx.z = fmaxf(mx.z, __shfl_xor_sync(0xffffffffu, mx.z, o));
            mx.w = fmaxf(mx.w, __shfl_xor_sync(0xffffffffu, mx.w, o));
        }
        float4 sum = make_float4(0.f, 0.f, 0.f, 0.f);
#pragma unroll
        for (int c = 0; c < 4; c++) {
            if (c < nc) {
                lg[c].x = __expf(lg[c].x - mx.x);
                lg[c].y = __expf(lg[c].y - mx.y);
                lg[c].z = __expf(lg[c].z - mx.z);
                lg[c].w = __expf(lg[c].w - mx.w);
                sum.x += lg[c].x;
                sum.y += lg[c].y;
                sum.z += lg[c].z;
                sum.w += lg[c].w;
            }
        }
#pragma unroll
        for (int o = 16; o; o >>= 1) {
            sum.x += __shfl_xor_sync(0xffffffffu, sum.x, o);
            sum.y += __shfl_xor_sync(0xffffffffu, sum.y, o);
            sum.z += __shfl_xor_sync(0xffffffffu, sum.z, o);
            sum.w += __shfl_xor_sync(0xffffffffu, sum.w, o);
        }
        float4 inv;
        inv.x = 1.f / (sum.x + 1e-9f);
        inv.y = 1.f / (sum.y + 1e-9f);
        inv.z = 1.f / (sum.z + 1e-9f);
        inv.w = 1.f / (sum.w + 1e-9f);
#pragma unroll
        for (int c = 0; c < 4; c++) {
            int k = st + lane + c * 32;
            if (k < en) {
                float4 av;
                av.x = lg[c].x * inv.x;
                av.y = lg[c].y * inv.y;
                av.z = lg[c].z * inv.z;
                av.w = lg[c].w * inv.w;
                if (ramix) {
                    float4 r = *reinterpret_cast<const float4*>(&ramix[(size_t)k * 4]);
                    av.x = av.x * 0.95f + 0.05f * r.x;
                    av.y = av.y * 0.95f + 0.05f * r.y;
                    av.z = av.z * 0.95f + 0.05f * r.z;
                    av.w = av.w * 0.95f + 0.05f * r.w;
                }
                *reinterpret_cast<float4*>(&aout[(size_t)k * 4]) = av;
            }
        }
        return;
    }

    for (int k = st + lane; k < en; k += 32) {
        int s = g_src_csr[k], t = g_et_csr[k];
        float4 a = *reinterpret_cast<const float4*>(&el[s * 4]);
        float4 c = *reinterpret_cast<const float4*>(&es[t * 4]);
        float4 lg;
        lg.x = lrelu(a.x + ern.x + c.x);
        lg.y = lrelu(a.y + ern.y + c.y);
        lg.z = lrelu(a.z + ern.z + c.z);
        lg.w = lrelu(a.w + ern.w + c.w);
        *reinterpret_cast<float4*>(&g_logits[(size_t)k * 4]) = lg;
        mx.x = fmaxf(mx.x, lg.x);
        mx.y = fmaxf(mx.y, lg.y);
        mx.z = fmaxf(mx.z, lg.z);
        mx.w = fmaxf(mx.w, lg.w);
    }
#pragma unroll
    for (int o = 16; o; o >>= 1) {
        mx.x = fmaxf(mx.x, __shfl_xor_sync(0xffffffffu, mx.x, o));
        mx.y = fmaxf(mx.y, __shfl_xor_sync(0xffffffffu, mx.y, o));
        mx.z = fmaxf(mx.z, __shfl_xor_sync(0xffffffffu, mx.z, o));
        mx.w = fmaxf(mx.w, __shfl_xor_sync(0xffffffffu, mx.w, o));
    }
    float4 sum = make_float4(0.f, 0.f, 0.f, 0.f);
    for (int k = st + lane; k < en; k += 32) {
        float4 lg = *reinterpret_cast<const float4*>(&g_logits[(size_t)k * 4]);
        float4 ex;
        ex.x = __expf(lg.x - mx.x);
        ex.y = __expf(lg.y - mx.y);
        ex.z = __expf(lg.z - mx.z);
        ex.w = __expf(lg.w - mx.w);
        *reinterpret_cast<float4*>(&g_logits[(size_t)k * 4]) = ex;
        sum.x += ex.x;
        sum.y += ex.y;
        sum.z += ex.z;
        sum.w += ex.w;
    }
#pragma unroll
    for (int o = 16; o; o >>= 1) {
        sum.x += __shfl_xor_sync(0xffffffffu, sum.x, o);
        sum.y += __shfl_xor_sync(0xffffffffu, sum.y, o);
        sum.z += __shfl_xor_sync(0xffffffffu, sum.z, o);
        sum.w += __shfl_xor_sync(0xffffffffu, sum.w, o);
    }
    float4 inv;
    inv.x = 1.f / (sum.x + 1e-9f);
    inv.y = 1.f / (sum.y + 1e-9f);
    inv.z = 1.f / (sum.z + 1e-9f);
    inv.w = 1.f / (sum.w + 1e-9f);
    for (int k = st + lane; k < en; k += 32) {
        float4 ex = *reinterpret_cast<const float4*>(&g_logits[(size_t)k * 4]);
        float4 av;
        av.x = ex.x * inv.x;
        av.y = ex.y * inv.y;
        av.z = ex.z * inv.z;
        av.w = ex.w * inv.w;
        if (ramix) {
            float4 r = *reinterpret_cast<const float4*>(&ramix[(size_t)k * 4]);
            av.x = av.x * 0.95f + 0.05f * r.x;
            av.y = av.y * 0.95f + 0.05f * r.y;
            av.z = av.z * 0.95f + 0.05f * r.z;
            av.w = av.w * 0.95f + 0.05f * r.w;
        }
        *reinterpret_cast<float4*>(&aout[(size_t)k * 4]) = av;
    }
}

// ---------------- aggregation: fp16 gather, 4-edge unroll per thread (MLP x4) ----------------
__global__ void k_agg4(const float* __restrict__ a, const __half* __restrict__ f16,
                       const float* __restrict__ res, float* __restrict__ out, int act) {
    int n = blockIdx.x;
    int t = threadIdx.x;
    int g = t >> 6;
    int i = t & 63;
    int h = i >> 4;
    int st = g_rowptr[n], en = g_rowptr[n + 1];
    const ull* f16v = reinterpret_cast<const ull*>(f16);
    float4 ac0 = make_float4(0.f, 0.f, 0.f, 0.f);
    float4 ac1 = make_float4(0.f, 0.f, 0.f, 0.f);
    float4 ac2 = make_float4(0.f, 0.f, 0.f, 0.f);
    float4 ac3 = make_float4(0.f, 0.f, 0.f, 0.f);
    int k = st + g;
    for (; k + 12 < en; k += 16) {
        int s0 = g_src_csr[k];
        int s1 = g_src_csr[k + 4];
        int s2 = g_src_csr[k + 8];
        int s3 = g_src_csr[k + 12];
        float a0 = __ldg(&a[(size_t)k * 4 + h]);
        float a1 = __ldg(&a[(size_t)(k + 4) * 4 + h]);
        float a2 = __ldg(&a[(size_t)(k + 8) * 4 + h]);
        float a3 = __ldg(&a[(size_t)(k + 12) * 4 + h]);
        ull v0 = __ldg(&f16v[(size_t)s0 * 64 + i]);
        ull v1 = __ldg(&f16v[(size_t)s1 * 64 + i]);
        ull v2 = __ldg(&f16v[(size_t)s2 * 64 + i]);
        ull v3 = __ldg(&f16v[(size_t)s3 * 64 + i]);
        hacc(ac0, a0, v0);
        hacc(ac1, a1, v1);
        hacc(ac2, a2, v2);
        hacc(ac3, a3, v3);
    }
    for (; k < en; k += 4) {
        int s = g_src_csr[k];
        float aw = __ldg(&a[(size_t)k * 4 + h]);
        ull v = __ldg(&f16v[(size_t)s * 64 + i]);
        hacc(ac0, aw, v);
    }
    float4 acc;
    acc.x = (ac0.x + ac1.x) + (ac2.x + ac3.x);
    acc.y = (ac0.y + ac1.y) + (ac2.y + ac3.y);
    acc.z = (ac0.z + ac1.z) + (ac2.z + ac3.z);
    acc.w = (ac0.w + ac1.w) + (ac2.w + ac3.w);
    __shared__ float sm[4][256];
    *reinterpret_cast<float4*>(&sm[g][i * 4]) = acc;
    __syncthreads();
    float v = (sm[0][t] + sm[1][t]) + (sm[2][t] + sm[3][t]);
    if (res) v += res[(size_t)n * 256 + t];
    if (act) v = v > 0.f ? v : __expf(v) - 1.f;
    out[(size_t)n * 256 + t] = v;
}

// ---------------- layer 2 ----------------
__global__ void k_copyB2(const float* __restrict__ Wg2, const float* __restrict__ resW2) {
    int i = blockIdx.x * blockDim.x + threadIdx.x;
    if (i < 16 * 256) g_B2[i] = Wg2[i];
    else if (i < 32 * 256) g_B2[i] = resW2[i - 16 * 256];
}

__global__ void k_attn1(const float* __restrict__ el, const float* __restrict__ er,
                        const float* __restrict__ es, float* __restrict__ aout) {
    int w = (blockIdx.x * blockDim.x + threadIdx.x) >> 5;
    int lane = threadIdx.x & 31;
    if (w >= NN) return;
    int st = g_rowptr[w], en = g_rowptr[w + 1];
    int deg = en - st;
    float ern = er[w];
    float mx = -1e30f;

    if (deg <= 128) {
        float lg[4];
        int nc = 0;
#pragma unroll
        for (int c = 0; c < 4; c++) {
            int k = st + lane + c * 32;
            if (k < en) {
                lg[c] = lrelu(el[g_src_csr[k]] + ern + es[g_et_csr[k]]);
                mx = fmaxf(mx, lg[c]);
                nc = c + 1;
            }
        }
#pragma unroll
        for (int o = 16; o; o >>= 1) mx = fmaxf(mx, __shfl_xor_sync(0xffffffffu, mx, o));
        float sum = 0.f;
#pragma unroll
        for (int c = 0; c < 4; c++) {
            if (c < nc) {
                lg[c] = __expf(lg[c] - mx);
                sum += lg[c];
            }
        }
#pragma unroll
        for (int o = 16; o; o >>= 1) sum += __shfl_xor_sync(0xffffffffu, sum, o);
        float inv = 1.f / (sum + 1e-9f);
#pragma unroll
        for (int c = 0; c < 4; c++) {
            int k = st + lane + c * 32;
            if (k < en) aout[k] = lg[c] * inv;
        }
        return;
    }

    for (int k = st + lane; k < en; k += 32) {
        float lg = lrelu(el[g_src_csr[k]] + ern + es[g_et_csr[k]]);
        g_logits[k] = lg;
        mx = fmaxf(mx, lg);
    }
#pragma unroll
    for (int o = 16; o; o >>= 1) mx = fmaxf(mx, __shfl_xor_sync(0xffffffffu, mx, o));
    float sum = 0.f;
    for (int k = st + lane; k < en; k += 32) {
        float ex = __expf(g_logits[k] - mx);
        g_logits[k] = ex;
        sum += ex;
    }
#pragma unroll
    for (int o = 16; o; o >>= 1) sum += __shfl_xor_sync(0xffffffffu, sum, o);
    float inv = 1.f / (sum + 1e-9f);
    for (int k = st + lane; k < en; k += 32) aout[k] = g_logits[k] * inv;
}

__global__ void k_agg2(const float* __restrict__ a, const float* __restrict__ fr,
                       float* __restrict__ out) {
    int i = blockIdx.x * blockDim.x + threadIdx.x;
    if (i >= NN * 16) return;
    int n = i >> 4, c = i & 15;
    int st = g_rowptr[n], en = g_rowptr[n + 1];
    float acc0 = 0.f, acc1 = 0.f;
    int k = st;
    for (; k + 1 < en; k += 2) {
        acc0 += __ldg(&a[k]) * __ldg(&fr[(size_t)g_src_csr[k] * 32 + c]);
        acc1 += __ldg(&a[k + 1]) * __ldg(&fr[(size_t)g_src_csr[k + 1] * 32 + c]);
    }
    if (k < en) acc0 += __ldg(&a[k]) * __ldg(&fr[(size_t)g_src_csr[k] * 32 + c]);
    out[i] = acc0 + acc1 + fr[(size_t)n * 32 + 16 + c];
}

// ---------------- host orchestration ----------------
static inline int cdiv(int a, int b) { return (a + b - 1) / b; }

extern "C" void kernel_launch(void* const* d_in, const int* in_sizes, int n_in,
                              void* d_out, int out_size) {
    (void)in_sizes;
    (void)n_in;
    (void)out_size;
    const float* x0 = (const float*)d_in[0];
    const float* x1 = (const float*)d_in[1];
    const float* x2 = (const float*)d_in[2];
    const int* src = (const int*)d_in[3];
    const int* dst = (const int*)d_in[4];
    const int* efeat = (const int*)d_in[5];
    const float* W0 = (const float*)d_in[6];
    const float* b0 = (const float*)d_in[7];
    const float* W1 = (const float*)d_in[8];
    const float* b1 = (const float*)d_in[9];
    const float* W2 = (const float*)d_in[10];
    const float* b2 = (const float*)d_in[11];
    const float* Wg0 = (const float*)d_in[12];
    const float* etab0 = (const float*)d_in[13];
    const float* We0 = (const float*)d_in[14];
    const float* al0 = (const float*)d_in[15];
    const float* ar0 = (const float*)d_in[16];
    const float* ae0 = (const float*)d_in[17];
    const float* Wg1 = (const float*)d_in[18];
    const float* etab1 = (const float*)d_in[19];
    const float* We1 = (const float*)d_in[20];
    const float* al1 = (const float*)d_in[21];
    const float* ar1 = (const float*)d_in[22];
    const float* ae1 = (const float*)d_in[23];
    const float* Wg2 = (const float*)d_in[24];
    const float* etab2 = (const float*)d_in[25];
    const float* We2 = (const float*)d_in[26];
    const float* al2 = (const float*)d_in[27];
    const float* ar2 = (const float*)d_in[28];
    const float* ae2 = (const float*)d_in[29];
    const float* resW2 = (const float*)d_in[30];
    float* out = (float*)d_out;

    void* p;
    cudaGetSymbolAddress(&p, g_feat);   float* dfeat2 = (float*)p;
    cudaGetSymbolAddress(&p, g_feat16); __half* dfeat16 = (__half*)p;
    cudaGetSymbolAddress(&p, g_out);    float* dout_l = (float*)p;
    cudaGetSymbolAddress(&p, g_el);     float* del = (float*)p;
    cudaGetSymbolAddress(&p, g_er);     float* der = (float*)p;
    cudaGetSymbolAddress(&p, g_a);      float* da = (float*)p;
    cudaGetSymbolAddress(&p, g_ra);     float* dra = (float*)p;
    cudaGetSymbolAddress(&p, g_es3);    float* des = (float*)p;
    cudaGetSymbolAddress(&p, g_B2);     float* dB2 = (float*)p;
    cudaGetSymbolAddress(&p, g_Wf);     float* dWf = (float*)p;
    cudaGetSymbolAddress(&p, g_cf);     float* dcf = (float*)p;
    cudaGetSymbolAddress(&p, g_deg);    int* ddeg = (int*)p;

    static cudaStream_t s2 = nullptr;
    static cudaEvent_t evFork = nullptr, evJoin = nullptr;
    if (!s2) {
        cudaStreamCreate(&s2);
        cudaEventCreateWithFlags(&evFork, cudaEventDisableTiming);
        cudaEventCreateWithFlags(&evJoin, cudaEventDisableTiming);
    }

    // ---- fork side stream: CSR build + es tables + B2 concat ----
    cudaEventRecord(evFork, 0);
    cudaStreamWaitEvent(s2, evFork, 0);
    k_zero_int<<<cdiv(NN, 256), 256, 0, s2>>>(ddeg, NN);
    k_hist<<<cdiv(EE, 256), 256, 0, s2>>>(dst);
    k_scan<<<1, 1024, 0, s2>>>();
    k_scatter<<<cdiv(EE, 256), 256, 0, s2>>>(src, dst, efeat);
    k_es<<<NETT * HH, 64, 0, s2>>>(etab0, We0, ae0, des + 0, HH);
    k_es<<<NETT * HH, 64, 0, s2>>>(etab1, We1, ae1, des + 32, HH);
    k_es<<<NETT * 1, 64, 0, s2>>>(etab2, We2, ae2, des + 64, 1);
    k_copyB2<<<cdiv(32 * 256, 256), 256, 0, s2>>>(Wg2, resW2);
    cudaEventRecord(evJoin, s2);

    // ---- main stream: weight fusion + single-launch segmented feat GEMM ----
    {
        dim3 gw(1, 256);
        k_wfuse_all<<<gw, 256>>>(Wg0, W0, W1, W2, b0, b1, b2, dWf, dcf);
    }
    {
        dim3 gg(SEG0 + SEG1 + SEG1, 2);
        gemm_feat_in<<<gg, 256>>>(x0, x1, x2, dWf, dcf, dfeat16, al0, ar0, del, der);
    }

    cudaStreamWaitEvent(0, evJoin, 0);

    // ---- GAT layer 0 ----
    {
        k_attn4<<<cdiv(NN * 32, 256), 256>>>(del, der, des + 0, dra, nullptr);
        k_agg4<<<NN, 256>>>(dra, dfeat16, nullptr, dout_l, 1);
    }

    // ---- GAT layer 1 ----
    {
        dim3 gg(cdiv(NN, GBM), 2);
        gemm_feat<<<gg, 256>>>(dout_l, Wg1, dfeat16, al1, ar1, del, der, NN, HDIM);
        k_attn4<<<cdiv(NN * 32, 256), 256>>>(del, der, des + 32, da, dra);
        k_agg4<<<NN, 256>>>(da, dfeat16, dout_l, dout_l, 1);
    }

    // ---- GAT layer 2 (H=1, C=16) ----
    {
        gemm_nt_s<<<cdiv(NN, 128), 256>>>(dout_l, dB2, dfeat2, al2, ar2, del, der, NN, HDIM);
        k_attn1<<<cdiv(NN * 32, 256), 256>>>(del, der, des + 64, da);
        k_agg2<<<cdiv(NN * 16, 256), 256>>>(da, dfeat2, out);
    }
}

// round 16
// speedup vs baseline: 1.0067x; 1.0067x over previous
#include <cuda_runtime.h>
#include <cuda_fp16.h>
#include <math.h>
#include <stdint.h>

#define NN 50000
#define EE 800000
#define HH 4
#define DD 64
#define HDIM 256
#define NETT 8
#define CCC 16

typedef unsigned long long ull;

// ---------------- scratch (static device globals; no allocs) ----------------
__device__ float g_feat[(size_t)NN * 32];      // layer-2 only: feat2|res2
__device__ __half g_feat16[(size_t)NN * HDIM];
__device__ float g_out[(size_t)NN * HDIM];
__device__ float g_el[NN * HH];
__device__ float g_er[NN * HH];
__device__ float g_logits[(size_t)EE * HH];
__device__ float g_a[(size_t)EE * HH];
__device__ float g_ra[(size_t)EE * HH];
__device__ float g_es3[3 * 32];
__device__ float g_B2[32 * HDIM];
__device__ float g_Wf[256 * (128 + 64 + 32)];
__device__ float g_cf[3 * 256];
__device__ int g_deg[NN];
__device__ int g_rowptr[NN + 1];
__device__ int g_fill[NN];
__device__ int g_src_csr[EE];
__device__ int g_et_csr[EE];

__device__ __forceinline__ float lrelu(float x) { return x > 0.f ? x : 0.2f * x; }

// packed f32x2 helpers
__device__ __forceinline__ ull pack2(float lo, float hi) {
    ull r;
    asm("mov.b64 %0, {%1, %2};" : "=l"(r) : "f"(lo), "f"(hi));
    return r;
}
__device__ __forceinline__ void unpack2(ull v, float& lo, float& hi) {
    asm("mov.b64 {%0, %1}, %2;" : "=f"(lo), "=f"(hi) : "l"(v));
}
__device__ __forceinline__ void ffma2(ull& d, ull a, ull b) {
    asm("fma.rn.f32x2 %0, %1, %2, %0;" : "+l"(d) : "l"(a), "l"(b));
}
__device__ __forceinline__ void hacc(float4& ac, float aw, ull v) {
    __half2 lo = *reinterpret_cast<__half2*>(&v);
    __half2 hi = *(reinterpret_cast<__half2*>(&v) + 1);
    float2 f01 = __half22float2(lo);
    float2 f23 = __half22float2(hi);
    ac.x += aw * f01.x;
    ac.y += aw * f01.y;
    ac.z += aw * f23.x;
    ac.w += aw * f23.y;
}

// ---------------- one-shot weight fusion ----------------
__global__ void k_wfuse_all(const float* __restrict__ Wg,
                            const float* __restrict__ W0, const float* __restrict__ W1,
                            const float* __restrict__ W2, const float* __restrict__ b0,
                            const float* __restrict__ b1, const float* __restrict__ b2,
                            float* __restrict__ Wf, float* __restrict__ cf) {
    int i = blockIdx.y;
    int j = threadIdx.x;
    const float* wg = Wg + i * 64;
    float s = 0.f;
    if (j < 128) {
#pragma unroll
        for (int k = 0; k < 64; k++) s += wg[k] * W0[k * 128 + j];
        Wf[i * 128 + j] = s;
    } else if (j < 192) {
        int jj = j - 128;
#pragma unroll
        for (int k = 0; k < 64; k++) s += wg[k] * W1[k * 64 + jj];
        Wf[256 * 128 + i * 64 + jj] = s;
    } else if (j < 224) {
        int jj = j - 192;
#pragma unroll
        for (int k = 0; k < 64; k++) s += wg[k] * W2[k * 32 + jj];
        Wf[256 * 192 + i * 32 + jj] = s;
    } else if (j < 227) {
        const float* b = (j == 224) ? b0 : (j == 225) ? b1 : b2;
#pragma unroll
        for (int k = 0; k < 64; k++) s += wg[k] * b[k];
        cf[(j - 224) * 256 + i] = s;
    }
}

// ---------------- CSR build ----------------
__global__ void k_zero_int(int* p, int n) {
    int i = blockIdx.x * blockDim.x + threadIdx.x;
    if (i < n) p[i] = 0;
}

__global__ void k_hist(const int* __restrict__ dst) {
    int e = blockIdx.x * blockDim.x + threadIdx.x;
    if (e < EE) atomicAdd(&g_deg[dst[e]], 1);
}

__global__ void k_scan() {
    __shared__ int sums[1024];
    const int T = 1024;
    const int CH = (NN + T - 1) / T;
    int t = threadIdx.x;
    int start = t * CH;
    int lim = min(start + CH, NN);
    int s = 0;
    for (int i = start; i < lim; i++) s += g_deg[i];
    sums[t] = s;
    __syncthreads();
    for (int off = 1; off < T; off <<= 1) {
        int v = (t >= off) ? sums[t - off] : 0;
        __syncthreads();
        sums[t] += v;
        __syncthreads();
    }
    int run = (t == 0) ? 0 : sums[t - 1];
    for (int i = start; i < lim; i++) {
        g_rowptr[i] = run;
        g_fill[i] = run;
        run += g_deg[i];
    }
    if (t == T - 1) g_rowptr[NN] = run;
}

__global__ void k_scatter(const int* __restrict__ src, const int* __restrict__ dst,
                          const int* __restrict__ et) {
    int e = blockIdx.x * blockDim.x + threadIdx.x;
    if (e < EE) {
        int p = atomicAdd(&g_fill[dst[e]], 1);
        g_src_csr[p] = src[e];
        g_et_csr[p] = et[e];
    }
}

// ---------------- skinny GEMM (128x32x32) + fused el2/er2 epilogue ----------------
__global__ void gemm_nt_s(const float* __restrict__ A, const float* __restrict__ B,
                          float* __restrict__ C, const float* __restrict__ al2,
                          const float* __restrict__ ar2, float* __restrict__ el,
                          float* __restrict__ er, int M, int K) {
    const int SBM = 128, SBN = 32, SBK = 32;
    __shared__ float As[SBK][SBM];
    __shared__ float Bs[SBK][SBN];
    int t = threadIdx.x;
    int tx = t & 7, ty = t >> 3;
    int bm = blockIdx.x * SBM;
    float acc[4][4] = {};
    for (int k0 = 0; k0 < K; k0 += SBK) {
#pragma unroll
        for (int q = 0; q < 4; q++) {
            int f = t + q * 256;
            int row = f >> 3, c4 = f & 7;
            int gr = bm + row;
            float4 v = make_float4(0.f, 0.f, 0.f, 0.f);
            if (gr < M) v = *reinterpret_cast<const float4*>(A + (size_t)gr * K + k0 + c4 * 4);
            As[c4 * 4 + 0][row] = v.x;
            As[c4 * 4 + 1][row] = v.y;
            As[c4 * 4 + 2][row] = v.z;
            As[c4 * 4 + 3][row] = v.w;
        }
        if (t < 256) {
            int row = t >> 3, c4 = t & 7;
            float4 w = *reinterpret_cast<const float4*>(B + (size_t)row * K + k0 + c4 * 4);
            Bs[c4 * 4 + 0][row] = w.x;
            Bs[c4 * 4 + 1][row] = w.y;
            Bs[c4 * 4 + 2][row] = w.z;
            Bs[c4 * 4 + 3][row] = w.w;
        }
        __syncthreads();
#pragma unroll
        for (int kk = 0; kk < SBK; kk++) {
            float4 ra = *reinterpret_cast<const float4*>(&As[kk][ty * 4]);
            float4 rb = *reinterpret_cast<const float4*>(&Bs[kk][tx * 4]);
            float av[4] = {ra.x, ra.y, ra.z, ra.w};
            float bv[4] = {rb.x, rb.y, rb.z, rb.w};
#pragma unroll
            for (int i = 0; i < 4; i++)
#pragma unroll
                for (int j = 0; j < 4; j++) acc[i][j] += av[i] * bv[j];
        }
        __syncthreads();
    }
    float alv[4] = {0.f, 0.f, 0.f, 0.f}, arv[4] = {0.f, 0.f, 0.f, 0.f};
    if (tx < 4) {
#pragma unroll
        for (int j = 0; j < 4; j++) {
            alv[j] = __ldg(&al2[tx * 4 + j]);
            arv[j] = __ldg(&ar2[tx * 4 + j]);
        }
    }
#pragma unroll
    for (int i = 0; i < 4; i++) {
        int gr = bm + ty * 4 + i;
        bool valid = gr < M;
        if (valid) {
            float4 v;
            v.x = acc[i][0];
            v.y = acc[i][1];
            v.z = acc[i][2];
            v.w = acc[i][3];
            *reinterpret_cast<float4*>(C + (size_t)gr * SBN + tx * 4) = v;
        }
        float pel = 0.f, per = 0.f;
        if (tx < 4) {
#pragma unroll
            for (int j = 0; j < 4; j++) {
                pel += acc[i][j] * alv[j];
                per += acc[i][j] * arv[j];
            }
        }
#pragma unroll
        for (int o = 1; o < 8; o <<= 1) {
            pel += __shfl_xor_sync(0xffffffffu, pel, o);
            per += __shfl_xor_sync(0xffffffffu, per, o);
        }
        if (tx == 0 && valid) {
            el[gr] = pel;
            er[gr] = per;
        }
    }
}

// ---------------- feat GEMM body (128x128x16, FFMA2, fused bias + el/er + fp16 out) ----------------
#define GBM 128
#define GBK 16

__device__ __forceinline__ void feat_body(int bx, int by, const float* __restrict__ A,
                                          const float* __restrict__ B,
                                          const float* __restrict__ cbias,
                                          __half* __restrict__ F16,
                                          const float* __restrict__ al,
                                          const float* __restrict__ ar,
                                          float* __restrict__ el, float* __restrict__ er,
                                          int M, int K) {
    __shared__ float2 As[2][GBK][GBM];
    __shared__ float Bs[2][GBK][128];
    int t = threadIdx.x;
    int tx = t & 15, ty = t >> 4;
    int bm = bx * GBM, bn = by * 128;
    int lrow = t >> 2;
    int lc4 = t & 3;

    float4 pa[2], pb[2];
    auto ldg = [&](int k0) {
#pragma unroll
        for (int q = 0; q < 2; q++) {
            int row = lrow + q * 64;
            int gr = bm + row;
            pa[q] = make_float4(0.f, 0.f, 0.f, 0.f);
            if (gr < M) pa[q] = *reinterpret_cast<const float4*>(A + (size_t)gr * K + k0 + lc4 * 4);
            int gc = bn + row;
            pb[q] = *reinterpret_cast<const float4*>(B + (size_t)gc * K + k0 + lc4 * 4);
        }
    };
    auto sts = [&](int buf) {
#pragma unroll
        for (int q = 0; q < 2; q++) {
            int row = lrow + q * 64;
            As[buf][lc4 * 4 + 0][row] = make_float2(pa[q].x, pa[q].x);
            As[buf][lc4 * 4 + 1][row] = make_float2(pa[q].y, pa[q].y);
            As[buf][lc4 * 4 + 2][row] = make_float2(pa[q].z, pa[q].z);
            As[buf][lc4 * 4 + 3][row] = make_float2(pa[q].w, pa[q].w);
            Bs[buf][lc4 * 4 + 0][row] = pb[q].x;
            Bs[buf][lc4 * 4 + 1][row] = pb[q].y;
            Bs[buf][lc4 * 4 + 2][row] = pb[q].z;
            Bs[buf][lc4 * 4 + 3][row] = pb[q].w;
        }
    };

    ull acc2[8][4];
#pragma unroll
    for (int i = 0; i < 8; i++)
#pragma unroll
        for (int j = 0; j < 4; j++) acc2[i][j] = 0ull;

    int nt = K / GBK;
    ldg(0);
    sts(0);
    __syncthreads();
    for (int it = 0; it < nt; it++) {
        int cur = it & 1;
        bool has = (it + 1) < nt;
        if (has) ldg((it + 1) * GBK);
#pragma unroll
        for (int kk = 0; kk < GBK; kk++) {
            const ull* ap0 = reinterpret_cast<const ull*>(&As[cur][kk][ty * 4]);
            const ull* ap1 = reinterpret_cast<const ull*>(&As[cur][kk][ty * 4 + 64]);
            ull aa[8];
            aa[0] = ap0[0]; aa[1] = ap0[1]; aa[2] = ap0[2]; aa[3] = ap0[3];
            aa[4] = ap1[0]; aa[5] = ap1[1]; aa[6] = ap1[2]; aa[7] = ap1[3];
            float4 b0 = *reinterpret_cast<const float4*>(&Bs[cur][kk][tx * 4]);
            float4 b1 = *reinterpret_cast<const float4*>(&Bs[cur][kk][tx * 4 + 64]);
            ull b2[4];
            b2[0] = pack2(b0.x, b0.y);
            b2[1] = pack2(b0.z, b0.w);
            b2[2] = pack2(b1.x, b1.y);
            b2[3] = pack2(b1.z, b1.w);
#pragma unroll
            for (int i = 0; i < 8; i++)
#pragma unroll
                for (int j = 0; j < 4; j++) ffma2(acc2[i][j], aa[i], b2[j]);
        }
        if (has) sts(cur ^ 1);
        __syncthreads();
    }

    int h0 = bn >> 6;
    float alv[2][4], arv[2][4], cv[2][4];
#pragma unroll
    for (int hj = 0; hj < 2; hj++)
#pragma unroll
        for (int j = 0; j < 4; j++) {
            alv[hj][j] = __ldg(&al[(h0 + hj) * 64 + tx * 4 + j]);
            arv[hj][j] = __ldg(&ar[(h0 + hj) * 64 + tx * 4 + j]);
            cv[hj][j] = cbias ? __ldg(&cbias[bn + hj * 64 + tx * 4 + j]) : 0.f;
        }
#pragma unroll
    for (int hi = 0; hi < 2; hi++) {
#pragma unroll
        for (int i = 0; i < 4; i++) {
            int gr = bm + ty * 4 + hi * 64 + i;
            bool valid = gr < M;
            float pel[2], per[2];
#pragma unroll
            for (int hj = 0; hj < 2; hj++) {
                float4 v;
                unpack2(acc2[hi * 4 + i][hj * 2 + 0], v.x, v.y);
                unpack2(acc2[hi * 4 + i][hj * 2 + 1], v.z, v.w);
                v.x += cv[hj][0];
                v.y += cv[hj][1];
                v.z += cv[hj][2];
                v.w += cv[hj][3];
                if (valid) {
                    __half2 lo = __floats2half2_rn(v.x, v.y);
                    __half2 hi2 = __floats2half2_rn(v.z, v.w);
                    ull pk;
                    asm("mov.b64 %0, {%1, %2};" : "=l"(pk)
                        : "r"(*reinterpret_cast<uint32_t*>(&lo)), "r"(*reinterpret_cast<uint32_t*>(&hi2)));
                    *reinterpret_cast<ull*>(F16 + (size_t)gr * HDIM + bn + hj * 64 + tx * 4) = pk;
                }
                pel[hj] = v.x * alv[hj][0] + v.y * alv[hj][1] + v.z * alv[hj][2] + v.w * alv[hj][3];
                per[hj] = v.x * arv[hj][0] + v.y * arv[hj][1] + v.z * arv[hj][2] + v.w * arv[hj][3];
            }
#pragma unroll
            for (int o = 1; o < 16; o <<= 1) {
                pel[0] += __shfl_xor_sync(0xffffffffu, pel[0], o);
                pel[1] += __shfl_xor_sync(0xffffffffu, pel[1], o);
                per[0] += __shfl_xor_sync(0xffffffffu, per[0], o);
                per[1] += __shfl_xor_sync(0xffffffffu, per[1], o);
            }
            if (tx == 0 && valid) {
                el[gr * 4 + h0] = pel[0];
                el[gr * 4 + h0 + 1] = pel[1];
                er[gr * 4 + h0] = per[0];
                er[gr * 4 + h0 + 1] = per[1];
            }
        }
    }
}

// layer-1 feat GEMM (single segment)
__global__ __launch_bounds__(256, 2) void gemm_feat(const float* __restrict__ A,
                                                    const float* __restrict__ B,
                                                    __half* __restrict__ F16,
                                                    const float* __restrict__ al,
                                                    const float* __restrict__ ar,
                                                    float* __restrict__ el,
                                                    float* __restrict__ er, int M, int K) {
    feat_body(blockIdx.x, blockIdx.y, A, B, nullptr, F16, al, ar, el, er, M, K);
}

// fused input-proj + layer-0 feat GEMM: 3 segments in one launch
#define SEG0 157
#define SEG1 118

__global__ __launch_bounds__(256, 2) void gemm_feat_in(const float* __restrict__ x0,
                                                       const float* __restrict__ x1,
                                                       const float* __restrict__ x2,
                                                       const float* __restrict__ Wf,
                                                       const float* __restrict__ cf,
                                                       __half* __restrict__ F16,
                                                       const float* __restrict__ al,
                                                       const float* __restrict__ ar,
                                                       float* __restrict__ el,
                                                       float* __restrict__ er) {
    int bx = blockIdx.x, by = blockIdx.y;
    if (bx < SEG0) {
        feat_body(bx, by, x0, Wf, cf, F16, al, ar, el, er, 20000, 128);
    } else if (bx < SEG0 + SEG1) {
        feat_body(bx - SEG0, by, x1, Wf + 256 * 128, cf + 256, F16 + (size_t)20000 * HDIM, al, ar,
                  el + 20000 * 4, er + 20000 * 4, 15000, 64);
    } else {
        feat_body(bx - SEG0 - SEG1, by, x2, Wf + 256 * 192, cf + 512, F16 + (size_t)35000 * HDIM,
                  al, ar, el + 35000 * 4, er + 35000 * 4, 15000, 32);
    }
}

// ---------------- edge-type attention term ----------------
__global__ void k_es(const float* __restrict__ etab, const float* __restrict__ We,
                     const float* __restrict__ ae, float* __restrict__ es, int H) {
    int b = blockIdx.x;
    int t = b / H, h = b % H;
    int d = threadIdx.x;
    const float* wr = We + (size_t)(h * 64 + d) * 64;
    const float* er = etab + t * 64;
    float dot = 0.f;
#pragma unroll
    for (int k = 0; k < 64; k++) dot += er[k] * wr[k];
    float v = ae[h * 64 + d] * dot;
    __shared__ float sm[64];
    sm[d] = v;
    __syncthreads();
    if (d < 32) {
        float x = sm[d] + sm[d + 32];
#pragma unroll
        for (int o = 16; o; o >>= 1) x += __shfl_xor_sync(0xffffffffu, x, o);
        if (d == 0) es[t * H + h] = x;
    }
}

// ---------------- fused logits + softmax (H=4), register-resident for deg<=128 ----------------
__global__ void k_attn4(const float* __restrict__ el, const float* __restrict__ er,
                        const float* __restrict__ es, float* __restrict__ aout,
                        const float* __restrict__ ramix) {
    int w = (blockIdx.x * blockDim.x + threadIdx.x) >> 5;
    int lane = threadIdx.x & 31;
    if (w >= NN) return;
    int st = g_rowptr[w], en = g_rowptr[w + 1];
    int deg = en - st;
    float4 ern = *reinterpret_cast<const float4*>(&er[w * 4]);
    float4 mx = make_float4(-1e30f, -1e30f, -1e30f, -1e30f);

    if (deg <= 128) {
        float4 lg[4];
        int nc = 0;
#pragma unroll
        for (int c = 0; c < 4; c++) {
            int k = st + lane + c * 32;
            if (k < en) {
                int s = g_src_csr[k], t = g_et_csr[k];
                float4 a = *reinterpret_cast<const float4*>(&el[s * 4]);
                float4 cc = *reinterpret_cast<const float4*>(&es[t * 4]);
                lg[c].x = lrelu(a.x + ern.x + cc.x);
                lg[c].y = lrelu(a.y + ern.y + cc.y);
                lg[c].z = lrelu(a.z + ern.z + cc.z);
                lg[c].w = lrelu(a.w + ern.w + cc.w);
                mx.x = fmaxf(mx.x, lg[c].x);
                mx.y = fmaxf(mx.y, lg[c].y);
                mx.z = fmaxf(mx.z, lg[c].z);
                mx.w = fmaxf(mx.w, lg[c].w);
                nc = c + 1;
            }
        }
#pragma unroll
        for (int o = 16; o; o >>= 1) {
            mx.x = fmaxf(mx.x, __shfl_xor_sync(0xffffffffu, mx.x, o));
            mx.y = fmaxf(mx.y, __shfl_xor_sync(0xffffffffu, mx.y, o));
            mx.z = fmaxf(mx.z, __shfl_xor_sync(0xffffffffu, mx.z, o));
            mx.w = fmaxf(mx.w, __shfl_xor_sync(0xffffffffu, mx.w, o));
        }
        float4 sum = make_float4(0.f, 0.f, 0.f, 0.f);
#pragma unroll
        for (int c = 0; c < 4; c++) {
            if (c < nc) {
                lg[c].x = __expf(lg[c].x - mx.x);
                lg[c].y = __expf(lg[c].y - mx.y);
                lg[c].z = __expf(lg[c].z - mx.z);
                lg[c].w = __expf(lg[c].w - mx.w);
                sum.x += lg[c].x;
                sum.y += lg[c].y;
                sum.z += lg[c].z;
                sum.w += lg[c].w;
            }
        }
#pragma unroll
        for (int o = 16; o; o >>= 1) {
            sum.x += __shfl_xor_sync(0xffffffffu, sum.x, o);
            sum.y += __shfl_xor_sync(0xffffffffu, sum.y, o);
            sum.z += __shfl_xor_sync(0xffffffffu, sum.z, o);
            sum.w += __shfl_xor_sync(0xffffffffu, sum.w, o);
        }
        float4 inv;
        inv.x = 1.f / (sum.x + 1e-9f);
        inv.y = 1.f / (sum.y + 1e-9f);
        inv.z = 1.f / (sum.z + 1e-9f);
        inv.w = 1.f / (sum.w + 1e-9f);
#pragma unroll
        for (int c = 0; c < 4; c++) {
            int k = st + lane + c * 32;
            if (k < en) {
                float4 av;
                av.x = lg[c].x * inv.x;
                av.y = lg[c].y * inv.y;
                av.z = lg[c].z * inv.z;
                av.w = lg[c].w * inv.w;
                if (ramix) {
                    float4 r = *reinterpret_cast<const float4*>(&ramix[(size_t)k * 4]);
                    av.x = av.x * 0.95f + 0.05f * r.x;
                    av.y = av.y * 0.95f + 0.05f * r.y;
                    av.z = av.z * 0.95f + 0.05f * r.z;
                    av.w = av.w * 0.95f + 0.05f * r.w;
                }
                *reinterpret_cast<float4*>(&aout[(size_t)k * 4]) = av;
            }
        }
        return;
    }

    for (int k = st + lane; k < en; k += 32) {
        int s = g_src_csr[k], t = g_et_csr[k];
        float4 a = *reinterpret_cast<const float4*>(&el[s * 4]);
        float4 c = *reinterpret_cast<const float4*>(&es[t * 4]);
        float4 lg;
        lg.x = lrelu(a.x + ern.x + c.x);
        lg.y = lrelu(a.y + ern.y + c.y);
        lg.z = lrelu(a.z + ern.z + c.z);
        lg.w = lrelu(a.w + ern.w + c.w);
        *reinterpret_cast<float4*>(&g_logits[(size_t)k * 4]) = lg;
        mx.x = fmaxf(mx.x, lg.x);
        mx.y = fmaxf(mx.y, lg.y);
        mx.z = fmaxf(mx.z, lg.z);
        mx.w = fmaxf(mx.w, lg.w);
    }
#pragma unroll
    for (int o = 16; o; o >>= 1) {
        mx.x = fmaxf(mx.x, __shfl_xor_sync(0xffffffffu, mx.x, o));
        mx.y = fmaxf(mx.y, __shfl_xor_sync(0xffffffffu, mx.y, o));
        mx.z = fmaxf(mx.z, __shfl_xor_sync(0xffffffffu, mx.z, o));
        mx.w = fmaxf(mx.w, __shfl_xor_sync(0xffffffffu, mx.w, o));
    }
    float4 sum = make_float4(0.f, 0.f, 0.f, 0.f);
    for (int k = st + lane; k < en; k += 32) {
        float4 lg = *reinterpret_cast<const float4*>(&g_logits[(size_t)k * 4]);
        float4 ex;
        ex.x = __expf(lg.x - mx.x);
        ex.y = __expf(lg.y - mx.y);
        ex.z = __expf(lg.z - mx.z);
        ex.w = __expf(lg.w - mx.w);
        *reinterpret_cast<float4*>(&g_logits[(size_t)k * 4]) = ex;
        sum.x += ex.x;
        sum.y += ex.y;
        sum.z += ex.z;
        sum.w += ex.w;
    }
#pragma unroll
    for (int o = 16; o; o >>= 1) {
        sum.x += __shfl_xor_sync(0xffffffffu, sum.x, o);
        sum.y += __shfl_xor_sync(0xffffffffu, sum.y, o);
        sum.z += __shfl_xor_sync(0xffffffffu, sum.z, o);
        sum.w += __shfl_xor_sync(0xffffffffu, sum.w, o);
    }
    float4 inv;
    inv.x = 1.f / (sum.x + 1e-9f);
    inv.y = 1.f / (sum.y + 1e-9f);
    inv.z = 1.f / (sum.z + 1e-9f);
    inv.w = 1.f / (sum.w + 1e-9f);
    for (int k = st + lane; k < en; k += 32) {
        float4 ex = *reinterpret_cast<const float4*>(&g_logits[(size_t)k * 4]);
        float4 av;
        av.x = ex.x * inv.x;
        av.y = ex.y * inv.y;
        av.z = ex.z * inv.z;
        av.w = ex.w * inv.w;
        if (ramix) {
            float4 r = *reinterpret_cast<const float4*>(&ramix[(size_t)k * 4]);
            av.x = av.x * 0.95f + 0.05f * r.x;
            av.y = av.y * 0.95f + 0.05f * r.y;
            av.z = av.z * 0.95f + 0.05f * r.z;
            av.w = av.w * 0.95f + 0.05f * r.w;
        }
        *reinterpret_cast<float4*>(&aout[(size_t)k * 4]) = av;
    }
}

// ---------------- aggregation: fp16 gather, 2-edge unroll per thread ----------------
__global__ void k_agg4(const float* __restrict__ a, const __half* __restrict__ f16,
                       const float* __restrict__ res, float* __restrict__ out, int act) {
    int n = blockIdx.x;
    int t = threadIdx.x;
    int g = t >> 6;
    int i = t & 63;
    int h = i >> 4;
    int st = g_rowptr[n], en = g_rowptr[n + 1];
    const ull* f16v = reinterpret_cast<const ull*>(f16);
    float4 ac0 = make_float4(0.f, 0.f, 0.f, 0.f);
    float4 ac1 = make_float4(0.f, 0.f, 0.f, 0.f);
    int k = st + g;
    for (; k + 4 < en; k += 8) {
        int s0 = g_src_csr[k];
        int s1 = g_src_csr[k + 4];
        float a0 = __ldg(&a[(size_t)k * 4 + h]);
        float a1 = __ldg(&a[(size_t)(k + 4) * 4 + h]);
        ull v0 = __ldg(&f16v[(size_t)s0 * 64 + i]);
        ull v1 = __ldg(&f16v[(size_t)s1 * 64 + i]);
        hacc(ac0, a0, v0);
        hacc(ac1, a1, v1);
    }
    if (k < en) {
        int s = g_src_csr[k];
        float aw = __ldg(&a[(size_t)k * 4 + h]);
        ull v = __ldg(&f16v[(size_t)s * 64 + i]);
        hacc(ac0, aw, v);
    }
    float4 acc;
    acc.x = ac0.x + ac1.x;
    acc.y = ac0.y + ac1.y;
    acc.z = ac0.z + ac1.z;
    acc.w = ac0.w + ac1.w;
    __shared__ float sm[4][256];
    *reinterpret_cast<float4*>(&sm[g][i * 4]) = acc;
    __syncthreads();
    float v = (sm[0][t] + sm[1][t]) + (sm[2][t] + sm[3][t]);
    if (res) v += res[(size_t)n * 256 + t];
    if (act) v = v > 0.f ? v : __expf(v) - 1.f;
    out[(size_t)n * 256 + t] = v;
}

// ---------------- layer 2 ----------------
__global__ void k_copyB2(const float* __restrict__ Wg2, const float* __restrict__ resW2) {
    int i = blockIdx.x * blockDim.x + threadIdx.x;
    if (i < 16 * 256) g_B2[i] = Wg2[i];
    else if (i < 32 * 256) g_B2[i] = resW2[i - 16 * 256];
}

__global__ void k_attn1(const float* __restrict__ el, const float* __restrict__ er,
                        const float* __restrict__ es, float* __restrict__ aout) {
    int w = (blockIdx.x * blockDim.x + threadIdx.x) >> 5;
    int lane = threadIdx.x & 31;
    if (w >= NN) return;
    int st = g_rowptr[w], en = g_rowptr[w + 1];
    int deg = en - st;
    float ern = er[w];
    float mx = -1e30f;

    if (deg <= 128) {
        float lg[4];
        int nc = 0;
#pragma unroll
        for (int c = 0; c < 4; c++) {
            int k = st + lane + c * 32;
            if (k < en) {
                lg[c] = lrelu(el[g_src_csr[k]] + ern + es[g_et_csr[k]]);
                mx = fmaxf(mx, lg[c]);
                nc = c + 1;
            }
        }
#pragma unroll
        for (int o = 16; o; o >>= 1) mx = fmaxf(mx, __shfl_xor_sync(0xffffffffu, mx, o));
        float sum = 0.f;
#pragma unroll
        for (int c = 0; c < 4; c++) {
            if (c < nc) {
                lg[c] = __expf(lg[c] - mx);
                sum += lg[c];
            }
        }
#pragma unroll
        for (int o = 16; o; o >>= 1) sum += __shfl_xor_sync(0xffffffffu, sum, o);
        float inv = 1.f / (sum + 1e-9f);
#pragma unroll
        for (int c = 0; c < 4; c++) {
            int k = st + lane + c * 32;
            if (k < en) aout[k] = lg[c] * inv;
        }
        return;
    }

    for (int k = st + lane; k < en; k += 32) {
        float lg = lrelu(el[g_src_csr[k]] + ern + es[g_et_csr[k]]);
        g_logits[k] = lg;
        mx = fmaxf(mx, lg);
    }
#pragma unroll
    for (int o = 16; o; o >>= 1) mx = fmaxf(mx, __shfl_xor_sync(0xffffffffu, mx, o));
    float sum = 0.f;
    for (int k = st + lane; k < en; k += 32) {
        float ex = __expf(g_logits[k] - mx);
        g_logits[k] = ex;
        sum += ex;
    }
#pragma unroll
    for (int o = 16; o; o >>= 1) sum += __shfl_xor_sync(0xffffffffu, sum, o);
    float inv = 1.f / (sum + 1e-9f);
    for (int k = st + lane; k < en; k += 32) aout[k] = g_logits[k] * inv;
}

__global__ void k_agg2(const float* __restrict__ a, const float* __restrict__ fr,
                       float* __restrict__ out) {
    int i = blockIdx.x * blockDim.x + threadIdx.x;
    if (i >= NN * 16) return;
    int n = i >> 4, c = i & 15;
    int st = g_rowptr[n], en = g_rowptr[n + 1];
    float acc0 = 0.f, acc1 = 0.f;
    int k = st;
    for (; k + 1 < en; k += 2) {
        acc0 += __ldg(&a[k]) * __ldg(&fr[(size_t)g_src_csr[k] * 32 + c]);
        acc1 += __ldg(&a[k + 1]) * __ldg(&fr[(size_t)g_src_csr[k + 1] * 32 + c]);
    }
    if (k < en) acc0 += __ldg(&a[k]) * __ldg(&fr[(size_t)g_src_csr[k] * 32 + c]);
    out[i] = acc0 + acc1 + fr[(size_t)n * 32 + 16 + c];
}

// ---------------- host orchestration ----------------
static inline int cdiv(int a, int b) { return (a + b - 1) / b; }

extern "C" void kernel_launch(void* const* d_in, const int* in_sizes, int n_in,
                              void* d_out, int out_size) {
    (void)in_sizes;
    (void)n_in;
    (void)out_size;
    const float* x0 = (const float*)d_in[0];
    const float* x1 = (const float*)d_in[1];
    const float* x2 = (const float*)d_in[2];
    const int* src = (const int*)d_in[3];
    const int* dst = (const int*)d_in[4];
    const int* efeat = (const int*)d_in[5];
    const float* W0 = (const float*)d_in[6];
    const float* b0 = (const float*)d_in[7];
    const float* W1 = (const float*)d_in[8];
    const float* b1 = (const float*)d_in[9];
    const float* W2 = (const float*)d_in[10];
    const float* b2 = (const float*)d_in[11];
    const float* Wg0 = (const float*)d_in[12];
    const float* etab0 = (const float*)d_in[13];
    const float* We0 = (const float*)d_in[14];
    const float* al0 = (const float*)d_in[15];
    const float* ar0 = (const float*)d_in[16];
    const float* ae0 = (const float*)d_in[17];
    const float* Wg1 = (const float*)d_in[18];
    const float* etab1 = (const float*)d_in[19];
    const float* We1 = (const float*)d_in[20];
    const float* al1 = (const float*)d_in[21];
    const float* ar1 = (const float*)d_in[22];
    const float* ae1 = (const float*)d_in[23];
    const float* Wg2 = (const float*)d_in[24];
    const float* etab2 = (const float*)d_in[25];
    const float* We2 = (const float*)d_in[26];
    const float* al2 = (const float*)d_in[27];
    const float* ar2 = (const float*)d_in[28];
    const float* ae2 = (const float*)d_in[29];
    const float* resW2 = (const float*)d_in[30];
    float* out = (float*)d_out;

    void* p;
    cudaGetSymbolAddress(&p, g_feat);   float* dfeat2 = (float*)p;
    cudaGetSymbolAddress(&p, g_feat16); __half* dfeat16 = (__half*)p;
    cudaGetSymbolAddress(&p, g_out);    float* dout_l = (float*)p;
    cudaGetSymbolAddress(&p, g_el);     float* del = (float*)p;
    cudaGetSymbolAddress(&p, g_er);     float* der = (float*)p;
    cudaGetSymbolAddress(&p, g_a);      float* da = (float*)p;
    cudaGetSymbolAddress(&p, g_ra);     float* dra = (float*)p;
    cudaGetSymbolAddress(&p, g_es3);    float* des = (float*)p;
    cudaGetSymbolAddress(&p, g_B2);     float* dB2 = (float*)p;
    cudaGetSymbolAddress(&p, g_Wf);     float* dWf = (float*)p;
    cudaGetSymbolAddress(&p, g_cf);     float* dcf = (float*)p;
    cudaGetSymbolAddress(&p, g_deg);    int* ddeg = (int*)p;

    static cudaStream_t s2 = nullptr;
    static cudaEvent_t evFork = nullptr, evJoin = nullptr;
    if (!s2) {
        cudaStreamCreate(&s2);
        cudaEventCreateWithFlags(&evFork, cudaEventDisableTiming);
        cudaEventCreateWithFlags(&evJoin, cudaEventDisableTiming);
    }

    // ---- fork side stream: CSR build + es tables + B2 concat ----
    cudaEventRecord(evFork, 0);
    cudaStreamWaitEvent(s2, evFork, 0);
    k_zero_int<<<cdiv(NN, 256), 256, 0, s2>>>(ddeg, NN);
    k_hist<<<cdiv(EE, 256), 256, 0, s2>>>(dst);
    k_scan<<<1, 1024, 0, s2>>>();
    k_scatter<<<cdiv(EE, 256), 256, 0, s2>>>(src, dst, efeat);
    k_es<<<NETT * HH, 64, 0, s2>>>(etab0, We0, ae0, des + 0, HH);
    k_es<<<NETT * HH, 64, 0, s2>>>(etab1, We1, ae1, des + 32, HH);
    k_es<<<NETT * 1, 64, 0, s2>>>(etab2, We2, ae2, des + 64, 1);
    k_copyB2<<<cdiv(32 * 256, 256), 256, 0, s2>>>(Wg2, resW2);
    cudaEventRecord(evJoin, s2);

    // ---- main stream: weight fusion + single-launch segmented feat GEMM ----
    {
        dim3 gw(1, 256);
        k_wfuse_all<<<gw, 256>>>(Wg0, W0, W1, W2, b0, b1, b2, dWf, dcf);
    }
    {
        dim3 gg(SEG0 + SEG1 + SEG1, 2);
        gemm_feat_in<<<gg, 256>>>(x0, x1, x2, dWf, dcf, dfeat16, al0, ar0, del, der);
    }

    cudaStreamWaitEvent(0, evJoin, 0);

    // ---- GAT layer 0 ----
    {
        k_attn4<<<cdiv(NN * 32, 256), 256>>>(del, der, des + 0, dra, nullptr);
        k_agg4<<<NN, 256>>>(dra, dfeat16, nullptr, dout_l, 1);
    }

    // ---- GAT layer 1 ----
    {
        dim3 gg(cdiv(NN, GBM), 2);
        gemm_feat<<<gg, 256>>>(dout_l, Wg1, dfeat16, al1, ar1, del, der, NN, HDIM);
        k_attn4<<<cdiv(NN * 32, 256), 256>>>(del, der, des + 32, da, dra);
        k_agg4<<<NN, 256>>>(da, dfeat16, dout_l, dout_l, 1);
    }

    // ---- GAT layer 2 (H=1, C=16) ----
    {
        gemm_nt_s<<<cdiv(NN, 128), 256>>>(dout_l, dB2, dfeat2, al2, ar2, del, der, NN, HDIM);
        k_attn1<<<cdiv(NN * 32, 256), 256>>>(del, der, des + 64, da);
        k_agg2<<<cdiv(NN * 16, 256), 256>>>(da, dfeat2, out);
    }
}

// round 17
// speedup vs baseline: 1.0986x; 1.0912x over previous
#include <cuda_runtime.h>
#include <cuda_fp16.h>
#include <math.h>
#include <stdint.h>

#define NN 50000
#define EE 800000
#define HH 4
#define DD 64
#define HDIM 256
#define NETT 8
#define CCC 16

typedef unsigned long long ull;

// ---------------- scratch (static device globals; no allocs) ----------------
__device__ float g_feat[(size_t)NN * 32];      // layer-2 only: feat2|res2
__device__ __half g_feat16[(size_t)NN * HDIM];
__device__ float g_out[(size_t)NN * HDIM];
__device__ float g_el[NN * HH];
__device__ float g_er[NN * HH];
__device__ float g_logits[(size_t)EE * HH];
__device__ float g_a[(size_t)EE * HH];
__device__ float g_ra[(size_t)EE * HH];
__device__ float g_es3[3 * 32];
__device__ float g_B2[32 * HDIM];
__device__ float g_Wf[256 * (128 + 64 + 32)];
__device__ float g_cf[3 * 256];
__device__ int g_deg[NN];
__device__ int g_rowptr[NN + 1];
__device__ int g_fill[NN];
__device__ int g_src_csr[EE];
__device__ int g_et_csr[EE];

__device__ __forceinline__ float lrelu(float x) { return x > 0.f ? x : 0.2f * x; }

// packed f32x2 helpers
__device__ __forceinline__ ull pack2(float lo, float hi) {
    ull r;
    asm("mov.b64 %0, {%1, %2};" : "=l"(r) : "f"(lo), "f"(hi));
    return r;
}
__device__ __forceinline__ void unpack2(ull v, float& lo, float& hi) {
    asm("mov.b64 {%0, %1}, %2;" : "=f"(lo), "=f"(hi) : "l"(v));
}
__device__ __forceinline__ void ffma2(ull& d, ull a, ull b) {
    asm("fma.rn.f32x2 %0, %1, %2, %0;" : "+l"(d) : "l"(a), "l"(b));
}
__device__ __forceinline__ void hacc(float4& ac, float aw, ull v) {
    __half2 lo = *reinterpret_cast<__half2*>(&v);
    __half2 hi = *(reinterpret_cast<__half2*>(&v) + 1);
    float2 f01 = __half22float2(lo);
    float2 f23 = __half22float2(hi);
    ac.x += aw * f01.x;
    ac.y += aw * f01.y;
    ac.z += aw * f23.x;
    ac.w += aw * f23.y;
}

// ---------------- one-shot weight fusion ----------------
__global__ void k_wfuse_all(const float* __restrict__ Wg,
                            const float* __restrict__ W0, const float* __restrict__ W1,
                            const float* __restrict__ W2, const float* __restrict__ b0,
                            const float* __restrict__ b1, const float* __restrict__ b2,
                            float* __restrict__ Wf, float* __restrict__ cf) {
    int i = blockIdx.y;
    int j = threadIdx.x;
    const float* wg = Wg + i * 64;
    float s = 0.f;
    if (j < 128) {
#pragma unroll
        for (int k = 0; k < 64; k++) s += wg[k] * W0[k * 128 + j];
        Wf[i * 128 + j] = s;
    } else if (j < 192) {
        int jj = j - 128;
#pragma unroll
        for (int k = 0; k < 64; k++) s += wg[k] * W1[k * 64 + jj];
        Wf[256 * 128 + i * 64 + jj] = s;
    } else if (j < 224) {
        int jj = j - 192;
#pragma unroll
        for (int k = 0; k < 64; k++) s += wg[k] * W2[k * 32 + jj];
        Wf[256 * 192 + i * 32 + jj] = s;
    } else if (j < 227) {
        const float* b = (j == 224) ? b0 : (j == 225) ? b1 : b2;
#pragma unroll
        for (int k = 0; k < 64; k++) s += wg[k] * b[k];
        cf[(j - 224) * 256 + i] = s;
    }
}

// ---------------- CSR build ----------------
__global__ void k_zero_int(int* p, int n) {
    int i = blockIdx.x * blockDim.x + threadIdx.x;
    if (i < n) p[i] = 0;
}

__global__ void k_hist(const int* __restrict__ dst) {
    int e = blockIdx.x * blockDim.x + threadIdx.x;
    if (e < EE) atomicAdd(&g_deg[dst[e]], 1);
}

__global__ void k_scan() {
    __shared__ int sums[1024];
    const int T = 1024;
    const int CH = (NN + T - 1) / T;
    int t = threadIdx.x;
    int start = t * CH;
    int lim = min(start + CH, NN);
    int s = 0;
    for (int i = start; i < lim; i++) s += g_deg[i];
    sums[t] = s;
    __syncthreads();
    for (int off = 1; off < T; off <<= 1) {
        int v = (t >= off) ? sums[t - off] : 0;
        __syncthreads();
        sums[t] += v;
        __syncthreads();
    }
    int run = (t == 0) ? 0 : sums[t - 1];
    for (int i = start; i < lim; i++) {
        g_rowptr[i] = run;
        g_fill[i] = run;
        run += g_deg[i];
    }
    if (t == T - 1) g_rowptr[NN] = run;
}

__global__ void k_scatter(const int* __restrict__ src, const int* __restrict__ dst,
                          const int* __restrict__ et) {
    int e = blockIdx.x * blockDim.x + threadIdx.x;
    if (e < EE) {
        int p = atomicAdd(&g_fill[dst[e]], 1);
        g_src_csr[p] = src[e];
        g_et_csr[p] = et[e];
    }
}

// ---------------- skinny GEMM (128x32x32) + fused el2/er2 epilogue ----------------
__global__ void gemm_nt_s(const float* __restrict__ A, const float* __restrict__ B,
                          float* __restrict__ C, const float* __restrict__ al2,
                          const float* __restrict__ ar2, float* __restrict__ el,
                          float* __restrict__ er, int M, int K) {
    const int SBM = 128, SBN = 32, SBK = 32;
    __shared__ float As[SBK][SBM];
    __shared__ float Bs[SBK][SBN];
    int t = threadIdx.x;
    int tx = t & 7, ty = t >> 3;
    int bm = blockIdx.x * SBM;
    float acc[4][4] = {};
    for (int k0 = 0; k0 < K; k0 += SBK) {
#pragma unroll
        for (int q = 0; q < 4; q++) {
            int f = t + q * 256;
            int row = f >> 3, c4 = f & 7;
            int gr = bm + row;
            float4 v = make_float4(0.f, 0.f, 0.f, 0.f);
            if (gr < M) v = *reinterpret_cast<const float4*>(A + (size_t)gr * K + k0 + c4 * 4);
            As[c4 * 4 + 0][row] = v.x;
            As[c4 * 4 + 1][row] = v.y;
            As[c4 * 4 + 2][row] = v.z;
            As[c4 * 4 + 3][row] = v.w;
        }
        if (t < 256) {
            int row = t >> 3, c4 = t & 7;
            float4 w = *reinterpret_cast<const float4*>(B + (size_t)row * K + k0 + c4 * 4);
            Bs[c4 * 4 + 0][row] = w.x;
            Bs[c4 * 4 + 1][row] = w.y;
            Bs[c4 * 4 + 2][row] = w.z;
            Bs[c4 * 4 + 3][row] = w.w;
        }
        __syncthreads();
#pragma unroll
        for (int kk = 0; kk < SBK; kk++) {
            float4 ra = *reinterpret_cast<const float4*>(&As[kk][ty * 4]);
            float4 rb = *reinterpret_cast<const float4*>(&Bs[kk][tx * 4]);
            float av[4] = {ra.x, ra.y, ra.z, ra.w};
            float bv[4] = {rb.x, rb.y, rb.z, rb.w};
#pragma unroll
            for (int i = 0; i < 4; i++)
#pragma unroll
                for (int j = 0; j < 4; j++) acc[i][j] += av[i] * bv[j];
        }
        __syncthreads();
    }
    float alv[4] = {0.f, 0.f, 0.f, 0.f}, arv[4] = {0.f, 0.f, 0.f, 0.f};
    if (tx < 4) {
#pragma unroll
        for (int j = 0; j < 4; j++) {
            alv[j] = __ldg(&al2[tx * 4 + j]);
            arv[j] = __ldg(&ar2[tx * 4 + j]);
        }
    }
#pragma unroll
    for (int i = 0; i < 4; i++) {
        int gr = bm + ty * 4 + i;
        bool valid = gr < M;
        if (valid) {
            float4 v;
            v.x = acc[i][0];
            v.y = acc[i][1];
            v.z = acc[i][2];
            v.w = acc[i][3];
            *reinterpret_cast<float4*>(C + (size_t)gr * SBN + tx * 4) = v;
        }
        float pel = 0.f, per = 0.f;
        if (tx < 4) {
#pragma unroll
            for (int j = 0; j < 4; j++) {
                pel += acc[i][j] * alv[j];
                per += acc[i][j] * arv[j];
            }
        }
#pragma unroll
        for (int o = 1; o < 8; o <<= 1) {
            pel += __shfl_xor_sync(0xffffffffu, pel, o);
            per += __shfl_xor_sync(0xffffffffu, per, o);
        }
        if (tx == 0 && valid) {
            el[gr] = pel;
            er[gr] = per;
        }
    }
}

// ---------------- feat GEMM body (128x128x16, FFMA2, fused bias + el/er + fp16 out) ----------------
#define GBM 128
#define GBK 16

__device__ __forceinline__ void feat_body(int bx, int by, const float* __restrict__ A,
                                          const float* __restrict__ B,
                                          const float* __restrict__ cbias,
                                          __half* __restrict__ F16,
                                          const float* __restrict__ al,
                                          const float* __restrict__ ar,
                                          float* __restrict__ el, float* __restrict__ er,
                                          int M, int K) {
    __shared__ float2 As[2][GBK][GBM];
    __shared__ float Bs[2][GBK][128];
    int t = threadIdx.x;
    int tx = t & 15, ty = t >> 4;
    int bm = bx * GBM, bn = by * 128;
    int lrow = t >> 2;
    int lc4 = t & 3;

    float4 pa[2], pb[2];
    auto ldg = [&](int k0) {
#pragma unroll
        for (int q = 0; q < 2; q++) {
            int row = lrow + q * 64;
            int gr = bm + row;
            pa[q] = make_float4(0.f, 0.f, 0.f, 0.f);
            if (gr < M) pa[q] = *reinterpret_cast<const float4*>(A + (size_t)gr * K + k0 + lc4 * 4);
            int gc = bn + row;
            pb[q] = *reinterpret_cast<const float4*>(B + (size_t)gc * K + k0 + lc4 * 4);
        }
    };
    auto sts = [&](int buf) {
#pragma unroll
        for (int q = 0; q < 2; q++) {
            int row = lrow + q * 64;
            As[buf][lc4 * 4 + 0][row] = make_float2(pa[q].x, pa[q].x);
            As[buf][lc4 * 4 + 1][row] = make_float2(pa[q].y, pa[q].y);
            As[buf][lc4 * 4 + 2][row] = make_float2(pa[q].z, pa[q].z);
            As[buf][lc4 * 4 + 3][row] = make_float2(pa[q].w, pa[q].w);
            Bs[buf][lc4 * 4 + 0][row] = pb[q].x;
            Bs[buf][lc4 * 4 + 1][row] = pb[q].y;
            Bs[buf][lc4 * 4 + 2][row] = pb[q].z;
            Bs[buf][lc4 * 4 + 3][row] = pb[q].w;
        }
    };

    ull acc2[8][4];
#pragma unroll
    for (int i = 0; i < 8; i++)
#pragma unroll
        for (int j = 0; j < 4; j++) acc2[i][j] = 0ull;

    int nt = K / GBK;
    ldg(0);
    sts(0);
    __syncthreads();
    for (int it = 0; it < nt; it++) {
        int cur = it & 1;
        bool has = (it + 1) < nt;
        if (has) ldg((it + 1) * GBK);
#pragma unroll
        for (int kk = 0; kk < GBK; kk++) {
            const ull* ap0 = reinterpret_cast<const ull*>(&As[cur][kk][ty * 4]);
            const ull* ap1 = reinterpret_cast<const ull*>(&As[cur][kk][ty * 4 + 64]);
            ull aa[8];
            aa[0] = ap0[0]; aa[1] = ap0[1]; aa[2] = ap0[2]; aa[3] = ap0[3];
            aa[4] = ap1[0]; aa[5] = ap1[1]; aa[6] = ap1[2]; aa[7] = ap1[3];
            float4 b0 = *reinterpret_cast<const float4*>(&Bs[cur][kk][tx * 4]);
            float4 b1 = *reinterpret_cast<const float4*>(&Bs[cur][kk][tx * 4 + 64]);
            ull b2[4];
            b2[0] = pack2(b0.x, b0.y);
            b2[1] = pack2(b0.z, b0.w);
            b2[2] = pack2(b1.x, b1.y);
            b2[3] = pack2(b1.z, b1.w);
#pragma unroll
            for (int i = 0; i < 8; i++)
#pragma unroll
                for (int j = 0; j < 4; j++) ffma2(acc2[i][j], aa[i], b2[j]);
        }
        if (has) sts(cur ^ 1);
        __syncthreads();
    }

    int h0 = bn >> 6;
    float alv[2][4], arv[2][4], cv[2][4];
#pragma unroll
    for (int hj = 0; hj < 2; hj++)
#pragma unroll
        for (int j = 0; j < 4; j++) {
            alv[hj][j] = __ldg(&al[(h0 + hj) * 64 + tx * 4 + j]);
            arv[hj][j] = __ldg(&ar[(h0 + hj) * 64 + tx * 4 + j]);
            cv[hj][j] = cbias ? __ldg(&cbias[bn + hj * 64 + tx * 4 + j]) : 0.f;
        }
#pragma unroll
    for (int hi = 0; hi < 2; hi++) {
#pragma unroll
        for (int i = 0; i < 4; i++) {
            int gr = bm + ty * 4 + hi * 64 + i;
            bool valid = gr < M;
            float pel[2], per[2];
#pragma unroll
            for (int hj = 0; hj < 2; hj++) {
                float4 v;
                unpack2(acc2[hi * 4 + i][hj * 2 + 0], v.x, v.y);
                unpack2(acc2[hi * 4 + i][hj * 2 + 1], v.z, v.w);
                v.x += cv[hj][0];
                v.y += cv[hj][1];
                v.z += cv[hj][2];
                v.w += cv[hj][3];
                if (valid) {
                    __half2 lo = __floats2half2_rn(v.x, v.y);
                    __half2 hi2 = __floats2half2_rn(v.z, v.w);
                    ull pk;
                    asm("mov.b64 %0, {%1, %2};" : "=l"(pk)
                        : "r"(*reinterpret_cast<uint32_t*>(&lo)), "r"(*reinterpret_cast<uint32_t*>(&hi2)));
                    *reinterpret_cast<ull*>(F16 + (size_t)gr * HDIM + bn + hj * 64 + tx * 4) = pk;
                }
                pel[hj] = v.x * alv[hj][0] + v.y * alv[hj][1] + v.z * alv[hj][2] + v.w * alv[hj][3];
                per[hj] = v.x * arv[hj][0] + v.y * arv[hj][1] + v.z * arv[hj][2] + v.w * arv[hj][3];
            }
#pragma unroll
            for (int o = 1; o < 16; o <<= 1) {
                pel[0] += __shfl_xor_sync(0xffffffffu, pel[0], o);
                pel[1] += __shfl_xor_sync(0xffffffffu, pel[1], o);
                per[0] += __shfl_xor_sync(0xffffffffu, per[0], o);
                per[1] += __shfl_xor_sync(0xffffffffu, per[1], o);
            }
            if (tx == 0 && valid) {
                el[gr * 4 + h0] = pel[0];
                el[gr * 4 + h0 + 1] = pel[1];
                er[gr * 4 + h0] = per[0];
                er[gr * 4 + h0 + 1] = per[1];
            }
        }
    }
}

// layer-1 feat GEMM (single segment)
__global__ __launch_bounds__(256, 2) void gemm_feat(const float* __restrict__ A,
                                                    const float* __restrict__ B,
                                                    __half* __restrict__ F16,
                                                    const float* __restrict__ al,
                                                    const float* __restrict__ ar,
                                                    float* __restrict__ el,
                                                    float* __restrict__ er, int M, int K) {
    feat_body(blockIdx.x, blockIdx.y, A, B, nullptr, F16, al, ar, el, er, M, K);
}

// fused input-proj + layer-0 feat GEMM: 3 segments in one launch
#define SEG0 157
#define SEG1 118

__global__ __launch_bounds__(256, 2) void gemm_feat_in(const float* __restrict__ x0,
                                                       const float* __restrict__ x1,
                                                       const float* __restrict__ x2,
                                                       const float* __restrict__ Wf,
                                                       const float* __restrict__ cf,
                                                       __half* __restrict__ F16,
                                                       const float* __restrict__ al,
                                                       const float* __restrict__ ar,
                                                       float* __restrict__ el,
                                                       float* __restrict__ er) {
    int bx = blockIdx.x, by = blockIdx.y;
    if (bx < SEG0) {
        feat_body(bx, by, x0, Wf, cf, F16, al, ar, el, er, 20000, 128);
    } else if (bx < SEG0 + SEG1) {
        feat_body(bx - SEG0, by, x1, Wf + 256 * 128, cf + 256, F16 + (size_t)20000 * HDIM, al, ar,
                  el + 20000 * 4, er + 20000 * 4, 15000, 64);
    } else {
        feat_body(bx - SEG0 - SEG1, by, x2, Wf + 256 * 192, cf + 512, F16 + (size_t)35000 * HDIM,
                  al, ar, el + 35000 * 4, er + 35000 * 4, 15000, 32);
    }
}

// ---------------- edge-type attention term ----------------
__global__ void k_es(const float* __restrict__ etab, const float* __restrict__ We,
                     const float* __restrict__ ae, float* __restrict__ es, int H) {
    int b = blockIdx.x;
    int t = b / H, h = b % H;
    int d = threadIdx.x;
    const float* wr = We + (size_t)(h * 64 + d) * 64;
    const float* er = etab + t * 64;
    float dot = 0.f;
#pragma unroll
    for (int k = 0; k < 64; k++) dot += er[k] * wr[k];
    float v = ae[h * 64 + d] * dot;
    __shared__ float sm[64];
    sm[d] = v;
    __syncthreads();
    if (d < 32) {
        float x = sm[d] + sm[d + 32];
#pragma unroll
        for (int o = 16; o; o >>= 1) x += __shfl_xor_sync(0xffffffffu, x, o);
        if (d == 0) es[t * H + h] = x;
    }
}

// ---------------- fused logits + softmax (H=4), register-resident for deg<=128 ----------------
__global__ void k_attn4(const float* __restrict__ el, const float* __restrict__ er,
                        const float* __restrict__ es, float* __restrict__ aout,
                        const float* __restrict__ ramix) {
    int w = (blockIdx.x * blockDim.x + threadIdx.x) >> 5;
    int lane = threadIdx.x & 31;
    if (w >= NN) return;
    int st = g_rowptr[w], en = g_rowptr[w + 1];
    int deg = en - st;
    float4 ern = *reinterpret_cast<const float4*>(&er[w * 4]);
    float4 mx = make_float4(-1e30f, -1e30f, -1e30f, -1e30f);

    if (deg <= 128) {
        float4 lg[4];
        int nc = 0;
#pragma unroll
        for (int c = 0; c < 4; c++) {
            int k = st + lane + c * 32;
            if (k < en) {
                int s = g_src_csr[k], t = g_et_csr[k];
                float4 a = *reinterpret_cast<const float4*>(&el[s * 4]);
                float4 cc = *reinterpret_cast<const float4*>(&es[t * 4]);
                lg[c].x = lrelu(a.x + ern.x + cc.x);
                lg[c].y = lrelu(a.y + ern.y + cc.y);
                lg[c].z = lrelu(a.z + ern.z + cc.z);
                lg[c].w = lrelu(a.w + ern.w + cc.w);
                mx.x = fmaxf(mx.x, lg[c].x);
                mx.y = fmaxf(mx.y, lg[c].y);
                mx.z = fmaxf(mx.z, lg[c].z);
                mx.w = fmaxf(mx.w, lg[c].w);
                nc = c + 1;
            }
        }
#pragma unroll
        for (int o = 16; o; o >>= 1) {
            mx.x = fmaxf(mx.x, __shfl_xor_sync(0xffffffffu, mx.x, o));
            mx.y = fmaxf(mx.y, __shfl_xor_sync(0xffffffffu, mx.y, o));
            mx.z = fmaxf(mx.z, __shfl_xor_sync(0xffffffffu, mx.z, o));
            mx.w = fmaxf(mx.w, __shfl_xor_sync(0xffffffffu, mx.w, o));
        }
        float4 sum = make_float4(0.f, 0.f, 0.f, 0.f);
#pragma unroll
        for (int c = 0; c < 4; c++) {
            if (c < nc) {
                lg[c].x = __expf(lg[c].x - mx.x);
                lg[c].y = __expf(lg[c].y - mx.y);
                lg[c].z = __expf(lg[c].z - mx.z);
                lg[c].w = __expf(lg[c].w - mx.w);
                sum.x += lg[c].x;
                sum.y += lg[c].y;
                sum.z += lg[c].z;
                sum.w += lg[c].w;
            }
        }
#pragma unroll
        for (int o = 16; o; o >>= 1) {
            sum.x += __shfl_xor_sync(0xffffffffu, sum.x, o);
            sum.y += __shfl_xor_sync(0xffffffffu, sum.y, o);
            sum.z += __shfl_xor_sync(0xffffffffu, sum.z, o);
            sum.w += __shfl_xor_sync(0xffffffffu, sum.w, o);
        }
        float4 inv;
        inv.x = 1.f / (sum.x + 1e-9f);
        inv.y = 1.f / (sum.y + 1e-9f);
        inv.z = 1.f / (sum.z + 1e-9f);
        inv.w = 1.f / (sum.w + 1e-9f);
#pragma unroll
        for (int c = 0; c < 4; c++) {
            int k = st + lane + c * 32;
            if (k < en) {
                float4 av;
                av.x = lg[c].x * inv.x;
                av.y = lg[c].y * inv.y;
                av.z = lg[c].z * inv.z;
                av.w = lg[c].w * inv.w;
                if (ramix) {
                    float4 r = *reinterpret_cast<const float4*>(&ramix[(size_t)k * 4]);
                    av.x = av.x * 0.95f + 0.05f * r.x;
                    av.y = av.y * 0.95f + 0.05f * r.y;
                    av.z = av.z * 0.95f + 0.05f * r.z;
                    av.w = av.w * 0.95f + 0.05f * r.w;
                }
                *reinterpret_cast<float4*>(&aout[(size_t)k * 4]) = av;
            }
        }
        return;
    }

    for (int k = st + lane; k < en; k += 32) {
        int s = g_src_csr[k], t = g_et_csr[k];
        float4 a = *reinterpret_cast<const float4*>(&el[s * 4]);
        float4 c = *reinterpret_cast<const float4*>(&es[t * 4]);
        float4 lg;
        lg.x = lrelu(a.x + ern.x + c.x);
        lg.y = lrelu(a.y + ern.y + c.y);
        lg.z = lrelu(a.z + ern.z + c.z);
        lg.w = lrelu(a.w + ern.w + c.w);
        *reinterpret_cast<float4*>(&g_logits[(size_t)k * 4]) = lg;
        mx.x = fmaxf(mx.x, lg.x);
        mx.y = fmaxf(mx.y, lg.y);
        mx.z = fmaxf(mx.z, lg.z);
        mx.w = fmaxf(mx.w, lg.w);
    }
#pragma unroll
    for (int o = 16; o; o >>= 1) {
        mx.x = fmaxf(mx.x, __shfl_xor_sync(0xffffffffu, mx.x, o));
        mx.y = fmaxf(mx.y, __shfl_xor_sync(0xffffffffu, mx.y, o));
        mx.z = fmaxf(mx.z, __shfl_xor_sync(0xffffffffu, mx.z, o));
        mx.w = fmaxf(mx.w, __shfl_xor_sync(0xffffffffu, mx.w, o));
    }
    float4 sum = make_float4(0.f, 0.f, 0.f, 0.f);
    for (int k = st + lane; k < en; k += 32) {
        float4 lg = *reinterpret_cast<const float4*>(&g_logits[(size_t)k * 4]);
        float4 ex;
        ex.x = __expf(lg.x - mx.x);
        ex.y = __expf(lg.y - mx.y);
        ex.z = __expf(lg.z - mx.z);
        ex.w = __expf(lg.w - mx.w);
        *reinterpret_cast<float4*>(&g_logits[(size_t)k * 4]) = ex;
        sum.x += ex.x;
        sum.y += ex.y;
        sum.z += ex.z;
        sum.w += ex.w;
    }
#pragma unroll
    for (int o = 16; o; o >>= 1) {
        sum.x += __shfl_xor_sync(0xffffffffu, sum.x, o);
        sum.y += __shfl_xor_sync(0xffffffffu, sum.y, o);
        sum.z += __shfl_xor_sync(0xffffffffu, sum.z, o);
        sum.w += __shfl_xor_sync(0xffffffffu, sum.w, o);
    }
    float4 inv;
    inv.x = 1.f / (sum.x + 1e-9f);
    inv.y = 1.f / (sum.y + 1e-9f);
    inv.z = 1.f / (sum.z + 1e-9f);
    inv.w = 1.f / (sum.w + 1e-9f);
    for (int k = st + lane; k < en; k += 32) {
        float4 ex = *reinterpret_cast<const float4*>(&g_logits[(size_t)k * 4]);
        float4 av;
        av.x = ex.x * inv.x;
        av.y = ex.y * inv.y;
        av.z = ex.z * inv.z;
        av.w = ex.w * inv.w;
        if (ramix) {
            float4 r = *reinterpret_cast<const float4*>(&ramix[(size_t)k * 4]);
            av.x = av.x * 0.95f + 0.05f * r.x;
            av.y = av.y * 0.95f + 0.05f * r.y;
            av.z = av.z * 0.95f + 0.05f * r.z;
            av.w = av.w * 0.95f + 0.05f * r.w;
        }
        *reinterpret_cast<float4*>(&aout[(size_t)k * 4]) = av;
    }
}

// ---------------- aggregation: fp16 feat gather, fp32 accumulate ----------------
__global__ void k_agg4(const float* __restrict__ a, const __half* __restrict__ f16,
                       const float* __restrict__ res, float* __restrict__ out, int act) {
    int n = blockIdx.x;
    int t = threadIdx.x;
    int g = t >> 6;
    int i = t & 63;
    int h = i >> 4;
    int st = g_rowptr[n], en = g_rowptr[n + 1];
    const ull* f16v = reinterpret_cast<const ull*>(f16);
    float4 acc = make_float4(0.f, 0.f, 0.f, 0.f);
    for (int k = st + g; k < en; k += 4) {
        int s = g_src_csr[k];
        float aw = __ldg(&a[(size_t)k * 4 + h]);
        ull v = __ldg(&f16v[(size_t)s * 64 + i]);
        __half2 lo = *reinterpret_cast<__half2*>(&v);
        __half2 hi = *(reinterpret_cast<__half2*>(&v) + 1);
        float2 f01 = __half22float2(lo);
        float2 f23 = __half22float2(hi);
        acc.x += aw * f01.x;
        acc.y += aw * f01.y;
        acc.z += aw * f23.x;
        acc.w += aw * f23.y;
    }
    __shared__ float sm[4][256];
    *reinterpret_cast<float4*>(&sm[g][i * 4]) = acc;
    __syncthreads();
    float v = (sm[0][t] + sm[1][t]) + (sm[2][t] + sm[3][t]);
    if (res) v += res[(size_t)n * 256 + t];
    if (act) v = v > 0.f ? v : __expf(v) - 1.f;
    out[(size_t)n * 256 + t] = v;
}

// ---------------- layer 2 ----------------
__global__ void k_copyB2(const float* __restrict__ Wg2, const float* __restrict__ resW2) {
    int i = blockIdx.x * blockDim.x + threadIdx.x;
    if (i < 16 * 256) g_B2[i] = Wg2[i];
    else if (i < 32 * 256) g_B2[i] = resW2[i - 16 * 256];
}

__global__ void k_attn1(const float* __restrict__ el, const float* __restrict__ er,
                        const float* __restrict__ es, float* __restrict__ aout) {
    int w = (blockIdx.x * blockDim.x + threadIdx.x) >> 5;
    int lane = threadIdx.x & 31;
    if (w >= NN) return;
    int st = g_rowptr[w], en = g_rowptr[w + 1];
    int deg = en - st;
    float ern = er[w];
    float mx = -1e30f;

    if (deg <= 128) {
        float lg[4];
        int nc = 0;
#pragma unroll
        for (int c = 0; c < 4; c++) {
            int k = st + lane + c * 32;
            if (k < en) {
                lg[c] = lrelu(el[g_src_csr[k]] + ern + es[g_et_csr[k]]);
                mx = fmaxf(mx, lg[c]);
                nc = c + 1;
            }
        }
#pragma unroll
        for (int o = 16; o; o >>= 1) mx = fmaxf(mx, __shfl_xor_sync(0xffffffffu, mx, o));
        float sum = 0.f;
#pragma unroll
        for (int c = 0; c < 4; c++) {
            if (c < nc) {
                lg[c] = __expf(lg[c] - mx);
                sum += lg[c];
            }
        }
#pragma unroll
        for (int o = 16; o; o >>= 1) sum += __shfl_xor_sync(0xffffffffu, sum, o);
        float inv = 1.f / (sum + 1e-9f);
#pragma unroll
        for (int c = 0; c < 4; c++) {
            int k = st + lane + c * 32;
            if (k < en) aout[k] = lg[c] * inv;
        }
        return;
    }

    for (int k = st + lane; k < en; k += 32) {
        float lg = lrelu(el[g_src_csr[k]] + ern + es[g_et_csr[k]]);
        g_logits[k] = lg;
        mx = fmaxf(mx, lg);
    }
#pragma unroll
    for (int o = 16; o; o >>= 1) mx = fmaxf(mx, __shfl_xor_sync(0xffffffffu, mx, o));
    float sum = 0.f;
    for (int k = st + lane; k < en; k += 32) {
        float ex = __expf(g_logits[k] - mx);
        g_logits[k] = ex;
        sum += ex;
    }
#pragma unroll
    for (int o = 16; o; o >>= 1) sum += __shfl_xor_sync(0xffffffffu, sum, o);
    float inv = 1.f / (sum + 1e-9f);
    for (int k = st + lane; k < en; k += 32) aout[k] = g_logits[k] * inv;
}

__global__ void k_agg2(const float* __restrict__ a, const float* __restrict__ fr,
                       float* __restrict__ out) {
    int i = blockIdx.x * blockDim.x + threadIdx.x;
    if (i >= NN * 16) return;
    int n = i >> 4, c = i & 15;
    int st = g_rowptr[n], en = g_rowptr[n + 1];
    float acc0 = 0.f, acc1 = 0.f;
    int k = st;
    for (; k + 1 < en; k += 2) {
        acc0 += __ldg(&a[k]) * __ldg(&fr[(size_t)g_src_csr[k] * 32 + c]);
        acc1 += __ldg(&a[k + 1]) * __ldg(&fr[(size_t)g_src_csr[k + 1] * 32 + c]);
    }
    if (k < en) acc0 += __ldg(&a[k]) * __ldg(&fr[(size_t)g_src_csr[k] * 32 + c]);
    out[i] = acc0 + acc1 + fr[(size_t)n * 32 + 16 + c];
}

// ---------------- host orchestration ----------------
static inline int cdiv(int a, int b) { return (a + b - 1) / b; }

extern "C" void kernel_launch(void* const* d_in, const int* in_sizes, int n_in,
                              void* d_out, int out_size) {
    (void)in_sizes;
    (void)n_in;
    (void)out_size;
    const float* x0 = (const float*)d_in[0];
    const float* x1 = (const float*)d_in[1];
    const float* x2 = (const float*)d_in[2];
    const int* src = (const int*)d_in[3];
    const int* dst = (const int*)d_in[4];
    const int* efeat = (const int*)d_in[5];
    const float* W0 = (const float*)d_in[6];
    const float* b0 = (const float*)d_in[7];
    const float* W1 = (const float*)d_in[8];
    const float* b1 = (const float*)d_in[9];
    const float* W2 = (const float*)d_in[10];
    const float* b2 = (const float*)d_in[11];
    const float* Wg0 = (const float*)d_in[12];
    const float* etab0 = (const float*)d_in[13];
    const float* We0 = (const float*)d_in[14];
    const float* al0 = (const float*)d_in[15];
    const float* ar0 = (const float*)d_in[16];
    const float* ae0 = (const float*)d_in[17];
    const float* Wg1 = (const float*)d_in[18];
    const float* etab1 = (const float*)d_in[19];
    const float* We1 = (const float*)d_in[20];
    const float* al1 = (const float*)d_in[21];
    const float* ar1 = (const float*)d_in[22];
    const float* ae1 = (const float*)d_in[23];
    const float* Wg2 = (const float*)d_in[24];
    const float* etab2 = (const float*)d_in[25];
    const float* We2 = (const float*)d_in[26];
    const float* al2 = (const float*)d_in[27];
    const float* ar2 = (const float*)d_in[28];
    const float* ae2 = (const float*)d_in[29];
    const float* resW2 = (const float*)d_in[30];
    float* out = (float*)d_out;

    void* p;
    cudaGetSymbolAddress(&p, g_feat);   float* dfeat2 = (float*)p;
    cudaGetSymbolAddress(&p, g_feat16); __half* dfeat16 = (__half*)p;
    cudaGetSymbolAddress(&p, g_out);    float* dout_l = (float*)p;
    cudaGetSymbolAddress(&p, g_el);     float* del = (float*)p;
    cudaGetSymbolAddress(&p, g_er);     float* der = (float*)p;
    cudaGetSymbolAddress(&p, g_a);      float* da = (float*)p;
    cudaGetSymbolAddress(&p, g_ra);     float* dra = (float*)p;
    cudaGetSymbolAddress(&p, g_es3);    float* des = (float*)p;
    cudaGetSymbolAddress(&p, g_B2);     float* dB2 = (float*)p;
    cudaGetSymbolAddress(&p, g_Wf);     float* dWf = (float*)p;
    cudaGetSymbolAddress(&p, g_cf);     float* dcf = (float*)p;
    cudaGetSymbolAddress(&p, g_deg);    int* ddeg = (int*)p;

    static cudaStream_t s2 = nullptr;
    static cudaEvent_t evFork = nullptr, evJoin = nullptr;
    if (!s2) {
        cudaStreamCreate(&s2);
        cudaEventCreateWithFlags(&evFork, cudaEventDisableTiming);
        cudaEventCreateWithFlags(&evJoin, cudaEventDisableTiming);
    }

    // ---- fork side stream: CSR build + es tables + B2 concat ----
    cudaEventRecord(evFork, 0);
    cudaStreamWaitEvent(s2, evFork, 0);
    k_zero_int<<<cdiv(NN, 256), 256, 0, s2>>>(ddeg, NN);
    k_hist<<<cdiv(EE, 256), 256, 0, s2>>>(dst);
    k_scan<<<1, 1024, 0, s2>>>();
    k_scatter<<<cdiv(EE, 256), 256, 0, s2>>>(src, dst, efeat);
    k_es<<<NETT * HH, 64, 0, s2>>>(etab0, We0, ae0, des + 0, HH);
    k_es<<<NETT * HH, 64, 0, s2>>>(etab1, We1, ae1, des + 32, HH);
    k_es<<<NETT * 1, 64, 0, s2>>>(etab2, We2, ae2, des + 64, 1);
    k_copyB2<<<cdiv(32 * 256, 256), 256, 0, s2>>>(Wg2, resW2);
    cudaEventRecord(evJoin, s2);

    // ---- main stream: weight fusion + single-launch segmented feat GEMM ----
    {
        dim3 gw(1, 256);
        k_wfuse_all<<<gw, 256>>>(Wg0, W0, W1, W2, b0, b1, b2, dWf, dcf);
    }
    {
        dim3 gg(SEG0 + SEG1 + SEG1, 2);
        gemm_feat_in<<<gg, 256>>>(x0, x1, x2, dWf, dcf, dfeat16, al0, ar0, del, der);
    }

    cudaStreamWaitEvent(0, evJoin, 0);

    // ---- GAT layer 0 ----
    {
        k_attn4<<<cdiv(NN * 32, 256), 256>>>(del, der, des + 0, dra, nullptr);
        k_agg4<<<NN, 256>>>(dra, dfeat16, nullptr, dout_l, 1);
    }

    // ---- GAT layer 1 ----
    {
        dim3 gg(cdiv(NN, GBM), 2);
        gemm_feat<<<gg, 256>>>(dout_l, Wg1, dfeat16, al1, ar1, del, der, NN, HDIM);
        k_attn4<<<cdiv(NN * 32, 256), 256>>>(del, der, des + 32, da, dra);
        k_agg4<<<NN, 256>>>(da, dfeat16, dout_l, dout_l, 1);
    }

    // ---- GAT layer 2 (H=1, C=16) ----
    {
        gemm_nt_s<<<cdiv(NN, 128), 256>>>(dout_l, dB2, dfeat2, al2, ar2, del, der, NN, HDIM);
        k_attn1<<<cdiv(NN * 32, 256), 256>>>(del, der, des + 64, da);
        k_agg2<<<cdiv(NN * 16, 256), 256>>>(da, dfeat2, out);
    }
}